// round 2
// baseline (speedup 1.0000x reference)
#include <cuda_runtime.h>
#include <cstddef>

constexpr int cNU = 100000, cNM = 20000, cH = 64, cE = 1000000, cEL = 500000;

// ---- device scratch ----
__device__ float g_xu0[cNU * cH];
__device__ float g_cat_u[cNU * 192];
__device__ float g_cat_m[cNM * 192];
__device__ float g_agg_u[cNU * cH];
__device__ float g_agg_m[cNM * cH];
__device__ float g_hu[cNU * cH];
__device__ float g_hm[cNM * cH];
__device__ float g_z1[(size_t)cEL * 64];
__device__ float g_z2[(size_t)cEL * 32];
__device__ int g_cnt_u[cNU], g_cnt_m[cNM], g_pos_u[cNU], g_pos_m[cNM];
__device__ int g_off_u[cNU + 1], g_off_m[cNM + 1];
__device__ int g_adj_u[cE], g_adj_m[cE];
__device__ double g_stats[192];
__device__ float g_bnp[192];

__global__ void zero_kernel() {
    int i = blockIdx.x * blockDim.x + threadIdx.x;
    if (i < cNU) { g_cnt_u[i] = 0; g_pos_u[i] = 0; }
    if (i < cNM) { g_cnt_m[i] = 0; g_pos_m[i] = 0; }
    if (i < 192) g_stats[i] = 0.0;
}

__global__ void count_kernel(const int* __restrict__ eu, const int* __restrict__ em) {
    int e = blockIdx.x * blockDim.x + threadIdx.x;
    if (e < cE) { atomicAdd(&g_cnt_u[eu[e]], 1); atomicAdd(&g_cnt_m[em[e]], 1); }
}

// one block per array: block 0 scans users, block 1 movies
__global__ void __launch_bounds__(1024) scan_kernel() {
    const int* cnt = blockIdx.x ? g_cnt_m : g_cnt_u;
    int* off = blockIdx.x ? g_off_m : g_off_u;
    int n = blockIdx.x ? cNM : cNU;
    __shared__ int s[1024];
    __shared__ int carry;
    int t = threadIdx.x;
    if (t == 0) carry = 0;
    __syncthreads();
    for (int base = 0; base < n; base += 1024) {
        int i = base + t;
        int v = (i < n) ? cnt[i] : 0;
        int x = v;
        for (int d = 1; d < 1024; d <<= 1) {
            s[t] = x; __syncthreads();
            if (t >= d) x += s[t - d];
            __syncthreads();
        }
        if (i < n) off[i] = carry + x - v;
        if (t == 1023) carry += x;
        __syncthreads();
    }
    if (t == 0) off[n] = cE;
}

__global__ void fill_kernel(const int* __restrict__ eu, const int* __restrict__ em) {
    int e = blockIdx.x * blockDim.x + threadIdx.x;
    if (e < cE) {
        int u = eu[e], m = em[e];
        g_adj_m[g_off_m[m] + atomicAdd(&g_pos_m[m], 1)] = u;
        g_adj_u[g_off_u[u] + atomicAdd(&g_pos_u[u], 1)] = m;
    }
}

__global__ void gather_u0_kernel(const int* __restrict__ n_id, const float* __restrict__ ue) {
    int i = blockIdx.x * blockDim.x + threadIdx.x;
    if (i < cNU * 16) {
        int r = i >> 4, c = i & 15;
        ((float4*)g_xu0)[r * 16 + c] = ((const float4*)ue)[(size_t)n_id[r] * 16 + c];
    }
}

// warp per destination node: mean of neighbor rows
__global__ void agg_mean_kernel(const float* __restrict__ src, int lds,
                                const int* __restrict__ adj, const int* __restrict__ off,
                                float* __restrict__ agg, int ndst) {
    int w = (blockIdx.x * blockDim.x + threadIdx.x) >> 5;
    int lane = threadIdx.x & 31;
    if (w >= ndst) return;
    int beg = off[w], end = off[w + 1];
    float ax = 0.f, ay = 0.f;
#pragma unroll 4
    for (int e = beg; e < end; ++e) {
        int s = __ldg(adj + e);
        float2 v = *(const float2*)(src + (size_t)s * lds + lane * 2);
        ax += v.x; ay += v.y;
    }
    float inv = (end > beg) ? 1.f / (float)(end - beg) : 0.f;
    *(float2*)(agg + (size_t)w * 64 + lane * 2) = make_float2(ax * inv, ay * inv);
}

// ---- GEMM core: 128 threads, 128-row tile, thread owns rows rowg+16i, cols colg*CPT.. ----
template <int K, int N>
__device__ __forceinline__ void gemm_compute(const float* __restrict__ sA,
                                             const float* __restrict__ sW,
                                             float acc[8][N / 8]) {
    constexpr int LDA = K + 2, CPT = N / 8;
    const int rowg = threadIdx.x & 15, colg = threadIdx.x >> 4;
    const float* aB = sA + rowg * LDA;
    const float* wB = sW + colg * CPT;
#pragma unroll 8
    for (int kk = 0; kk < K; kk += 2) {
        float2 a[8];
#pragma unroll
        for (int i = 0; i < 8; ++i) a[i] = *(const float2*)(aB + i * 16 * LDA + kk);
        float w0[CPT], w1[CPT];
#pragma unroll
        for (int j = 0; j < CPT; j += 4) {
            float4 t = *(const float4*)(wB + kk * N + j);
            w0[j] = t.x; w0[j + 1] = t.y; w0[j + 2] = t.z; w0[j + 3] = t.w;
            float4 u = *(const float4*)(wB + (kk + 1) * N + j);
            w1[j] = u.x; w1[j + 1] = u.y; w1[j + 2] = u.z; w1[j + 3] = u.w;
        }
#pragma unroll
        for (int i = 0; i < 8; ++i)
#pragma unroll
            for (int j = 0; j < CPT; ++j)
                acc[i][j] = fmaf(a[i].x, w0[j], fmaf(a[i].y, w1[j], acc[i][j]));
    }
}

constexpr int SAGE_SMEM = (128 * 130 + 128 * 64) * 4;
constexpr int PROJ_SMEM = (128 * 194 + 192 * 64) * 4;
constexpr int Z2_SMEM = (128 * 66 + 64 * 32) * 4;

// relu([agg | x] @ [Wl;Wr] + b)
__global__ void __launch_bounds__(128) sage_gemm_kernel(
    const float* __restrict__ agg, const float* __restrict__ x, int ldx,
    const float* __restrict__ Wl, const float* __restrict__ Wr,
    const float* __restrict__ bias, float* __restrict__ outp, int ldo, int nrows) {
    constexpr int LDA = 130;
    extern __shared__ float sm[];
    float* sA = sm;
    float* sW = sm + 128 * LDA;
    __shared__ float sB[64];
    const int tid = threadIdx.x, rowbase = blockIdx.x * 128;
    if (tid < 64) sB[tid] = bias[tid];
    for (int i = tid; i < 1024; i += 128) {
        ((float4*)sW)[i] = ((const float4*)Wl)[i];
        ((float4*)(sW + 4096))[i] = ((const float4*)Wr)[i];
    }
    for (int idx = tid; idx < 128 * 64; idx += 128) {
        int r = idx >> 6, c2 = idx & 63, g = rowbase + r, c = c2 * 2;
        float2 v = make_float2(0.f, 0.f);
        if (g < nrows)
            v = (c < 64) ? *(const float2*)(agg + (size_t)g * 64 + c)
                         : *(const float2*)(x + (size_t)g * ldx + (c - 64));
        *(float2*)(sA + r * LDA + c) = v;
    }
    __syncthreads();
    float acc[8][8];
#pragma unroll
    for (int i = 0; i < 8; ++i)
#pragma unroll
        for (int j = 0; j < 8; ++j) acc[i][j] = 0.f;
    gemm_compute<128, 64>(sA, sW, acc);
    const int rowg = tid & 15, colg = tid >> 4;
#pragma unroll
    for (int i = 0; i < 8; ++i) {
        int g = rowbase + rowg + 16 * i;
        if (g < nrows) {
            float o[8];
#pragma unroll
            for (int j = 0; j < 8; ++j) o[j] = fmaxf(acc[i][j] + sB[colg * 8 + j], 0.f);
            float* dst = outp + (size_t)g * ldo + colg * 8;
            *(float4*)dst = make_float4(o[0], o[1], o[2], o[3]);
            *(float4*)(dst + 4) = make_float4(o[4], o[5], o[6], o[7]);
        }
    }
}

// cat[*,192] @ W + b
__global__ void __launch_bounds__(128) proj_gemm_kernel(
    const float* __restrict__ A, const float* __restrict__ W,
    const float* __restrict__ bias, float* __restrict__ outp, int nrows) {
    constexpr int LDA = 194;
    extern __shared__ float sm[];
    float* sA = sm;
    float* sW = sm + 128 * LDA;
    __shared__ float sB[64];
    const int tid = threadIdx.x, rowbase = blockIdx.x * 128;
    if (tid < 64) sB[tid] = bias[tid];
    for (int i = tid; i < 192 * 16; i += 128) ((float4*)sW)[i] = ((const float4*)W)[i];
    for (int idx = tid; idx < 128 * 96; idx += 128) {
        int r = idx / 96, c2 = idx - r * 96, g = rowbase + r;
        float2 v = make_float2(0.f, 0.f);
        if (g < nrows) v = *(const float2*)(A + (size_t)g * 192 + c2 * 2);
        *(float2*)(sA + r * LDA + c2 * 2) = v;
    }
    __syncthreads();
    float acc[8][8];
#pragma unroll
    for (int i = 0; i < 8; ++i)
#pragma unroll
        for (int j = 0; j < 8; ++j) acc[i][j] = 0.f;
    gemm_compute<192, 64>(sA, sW, acc);
    const int rowg = tid & 15, colg = tid >> 4;
#pragma unroll
    for (int i = 0; i < 8; ++i) {
        int g = rowbase + rowg + 16 * i;
        if (g < nrows) {
            float o[8];
#pragma unroll
            for (int j = 0; j < 8; ++j) o[j] = acc[i][j] + sB[colg * 8 + j];
            float* dst = outp + (size_t)g * 64 + colg * 8;
            *(float4*)dst = make_float4(o[0], o[1], o[2], o[3]);
            *(float4*)(dst + 4) = make_float4(o[4], o[5], o[6], o[7]);
        }
    }
}

// gather [h_u[lu] | h_m[lm]] @ W1 + b1, write z1, accumulate BN stats
__global__ void __launch_bounds__(128) z1_kernel(
    const int* __restrict__ lu, const int* __restrict__ lm,
    const float* __restrict__ W1, const float* __restrict__ bias) {
    constexpr int LDA = 130;
    extern __shared__ float sm[];
    float* sA = sm;
    float* sW = sm + 128 * LDA;
    __shared__ float sB[64];
    __shared__ int sIU[128], sIM[128];
    const int tid = threadIdx.x, rowbase = blockIdx.x * 128;
    if (tid < 64) sB[tid] = bias[tid];
    {
        int g = rowbase + tid;
        sIU[tid] = (g < cEL) ? lu[g] : 0;
        sIM[tid] = (g < cEL) ? lm[g] : 0;
    }
    for (int i = tid; i < 2048; i += 128) ((float4*)sW)[i] = ((const float4*)W1)[i];
    __syncthreads();
    for (int idx = tid; idx < 128 * 64; idx += 128) {
        int r = idx >> 6, c2 = idx & 63, g = rowbase + r, c = c2 * 2;
        float2 v = make_float2(0.f, 0.f);
        if (g < cEL)
            v = (c < 64) ? *(const float2*)(g_hu + (size_t)sIU[r] * 64 + c)
                         : *(const float2*)(g_hm + (size_t)sIM[r] * 64 + (c - 64));
        *(float2*)(sA + r * LDA + c) = v;
    }
    __syncthreads();
    float acc[8][8];
#pragma unroll
    for (int i = 0; i < 8; ++i)
#pragma unroll
        for (int j = 0; j < 8; ++j) acc[i][j] = 0.f;
    gemm_compute<128, 64>(sA, sW, acc);
    const int rowg = tid & 15, colg = tid >> 4;
    float ls[8] = {0}, lq[8] = {0};
#pragma unroll
    for (int i = 0; i < 8; ++i) {
        int g = rowbase + rowg + 16 * i;
        if (g < cEL) {
            float o[8];
#pragma unroll
            for (int j = 0; j < 8; ++j) {
                o[j] = acc[i][j] + sB[colg * 8 + j];
                ls[j] += o[j]; lq[j] += o[j] * o[j];
            }
            float* dst = g_z1 + (size_t)g * 64 + colg * 8;
            *(float4*)dst = make_float4(o[0], o[1], o[2], o[3]);
            *(float4*)(dst + 4) = make_float4(o[4], o[5], o[6], o[7]);
        }
    }
    __syncthreads();
#pragma unroll
    for (int j = 0; j < 8; ++j) {
        sA[rowg * 64 + colg * 8 + j] = ls[j];
        sA[1024 + rowg * 64 + colg * 8 + j] = lq[j];
    }
    __syncthreads();
    if (tid < 64) {
        float s = 0.f, q = 0.f;
        for (int g2 = 0; g2 < 16; ++g2) { s += sA[g2 * 64 + tid]; q += sA[1024 + g2 * 64 + tid]; }
        atomicAdd(&g_stats[tid], (double)s);
        atomicAdd(&g_stats[64 + tid], (double)q);
    }
}

__global__ void bn_finalize_kernel(int soff, int boff, int n,
                                   const float* __restrict__ gamma,
                                   const float* __restrict__ beta, float invc) {
    int t = threadIdx.x;
    if (t < n) {
        double m = g_stats[soff + t] * invc;
        double v = g_stats[soff + n + t] * invc - m * m;
        float sc = gamma[t] * rsqrtf((float)v + 1e-5f);
        g_bnp[boff + t] = sc;
        g_bnp[boff + n + t] = beta[t] - (float)m * sc;
    }
}

// z2 = bn1relu(z1) @ W2 + b2, write raw z2, accumulate stats
__global__ void __launch_bounds__(128) z2_kernel(const float* __restrict__ W2,
                                                 const float* __restrict__ bias) {
    constexpr int LDA = 66;
    extern __shared__ float sm[];
    float* sA = sm;
    float* sW = sm + 128 * LDA;
    __shared__ float sB[32], sSc[64], sSh[64];
    const int tid = threadIdx.x, rowbase = blockIdx.x * 128;
    if (tid < 32) sB[tid] = bias[tid];
    if (tid < 64) { sSc[tid] = g_bnp[tid]; sSh[tid] = g_bnp[64 + tid]; }
    for (int i = tid; i < 512; i += 128) ((float4*)sW)[i] = ((const float4*)W2)[i];
    __syncthreads();
    for (int idx = tid; idx < 128 * 32; idx += 128) {
        int r = idx >> 5, c2 = idx & 31, g = rowbase + r, c = c2 * 2;
        float2 v = make_float2(0.f, 0.f);
        if (g < cEL) {
            float2 z = *(const float2*)(g_z1 + (size_t)g * 64 + c);
            v.x = fmaxf(z.x * sSc[c] + sSh[c], 0.f);
            v.y = fmaxf(z.y * sSc[c + 1] + sSh[c + 1], 0.f);
        }
        *(float2*)(sA + r * LDA + c) = v;
    }
    __syncthreads();
    float acc[8][4];
#pragma unroll
    for (int i = 0; i < 8; ++i)
#pragma unroll
        for (int j = 0; j < 4; ++j) acc[i][j] = 0.f;
    gemm_compute<64, 32>(sA, sW, acc);
    const int rowg = tid & 15, colg = tid >> 4;
    float ls[4] = {0}, lq[4] = {0};
#pragma unroll
    for (int i = 0; i < 8; ++i) {
        int g = rowbase + rowg + 16 * i;
        if (g < cEL) {
            float o[4];
#pragma unroll
            for (int j = 0; j < 4; ++j) {
                o[j] = acc[i][j] + sB[colg * 4 + j];
                ls[j] += o[j]; lq[j] += o[j] * o[j];
            }
            *(float4*)(g_z2 + (size_t)g * 32 + colg * 4) = make_float4(o[0], o[1], o[2], o[3]);
        }
    }
    __syncthreads();
#pragma unroll
    for (int j = 0; j < 4; ++j) {
        sA[rowg * 32 + colg * 4 + j] = ls[j];
        sA[512 + rowg * 32 + colg * 4 + j] = lq[j];
    }
    __syncthreads();
    if (tid < 32) {
        float s = 0.f, q = 0.f;
        for (int g2 = 0; g2 < 16; ++g2) { s += sA[g2 * 32 + tid]; q += sA[512 + g2 * 32 + tid]; }
        atomicAdd(&g_stats[128 + tid], (double)s);
        atomicAdd(&g_stats[160 + tid], (double)q);
    }
}

// out = bn2relu(z2) @ W3 + b3
__global__ void __launch_bounds__(256) z3_kernel(const float* __restrict__ W3,
                                                 const float* __restrict__ b3,
                                                 float* __restrict__ out) {
    __shared__ float sW[32], sSc[32], sSh[32];
    int tid = threadIdx.x;
    if (tid < 32) { sW[tid] = W3[tid]; sSc[tid] = g_bnp[128 + tid]; sSh[tid] = g_bnp[160 + tid]; }
    __syncthreads();
    int g = blockIdx.x * 256 + tid;
    if (g < cEL) {
        const float* row = g_z2 + (size_t)g * 32;
        float acc = 0.f;
#pragma unroll
        for (int c = 0; c < 32; c += 4) {
            float4 v = *(const float4*)(row + c);
            acc += fmaxf(v.x * sSc[c] + sSh[c], 0.f) * sW[c];
            acc += fmaxf(v.y * sSc[c + 1] + sSh[c + 1], 0.f) * sW[c + 1];
            acc += fmaxf(v.z * sSc[c + 2] + sSh[c + 2], 0.f) * sW[c + 2];
            acc += fmaxf(v.w * sSc[c + 3] + sSh[c + 3], 0.f) * sW[c + 3];
        }
        out[g] = acc + b3[0];
    }
}

extern "C" void kernel_launch(void* const* d_in, const int* in_sizes, int n_in,
                              void* d_out, int out_size) {
    const int* n_id = (const int*)d_in[0];
    const float* movie_x = (const float*)d_in[1];
    const int* eu = (const int*)d_in[2];
    const int* em = (const int*)d_in[3];
    const int* lu = (const int*)d_in[4];
    const int* lm = (const int*)d_in[5];
    const float* user_emb = (const float*)d_in[6];
    const float* Wl_um = (const float*)d_in[7];
    const float* b_um = (const float*)d_in[8];
    const float* Wr_um = (const float*)d_in[9];
    const float* Wl_mu = (const float*)d_in[10];
    const float* b_mu = (const float*)d_in[11];
    const float* Wr_mu = (const float*)d_in[12];
    const float* proj_u_W = (const float*)d_in[13];
    const float* proj_u_b = (const float*)d_in[14];
    const float* proj_m_W = (const float*)d_in[15];
    const float* proj_m_b = (const float*)d_in[16];
    const float* W1 = (const float*)d_in[17];
    const float* b1 = (const float*)d_in[18];
    const float* g1 = (const float*)d_in[19];
    const float* be1 = (const float*)d_in[20];
    const float* W2 = (const float*)d_in[21];
    const float* b2 = (const float*)d_in[22];
    const float* g2 = (const float*)d_in[23];
    const float* be2 = (const float*)d_in[24];
    const float* W3 = (const float*)d_in[25];
    const float* b3 = (const float*)d_in[26];
    float* out = (float*)d_out;

    cudaFuncSetAttribute(sage_gemm_kernel, cudaFuncAttributeMaxDynamicSharedMemorySize, SAGE_SMEM);
    cudaFuncSetAttribute(proj_gemm_kernel, cudaFuncAttributeMaxDynamicSharedMemorySize, PROJ_SMEM);
    cudaFuncSetAttribute(z1_kernel, cudaFuncAttributeMaxDynamicSharedMemorySize, SAGE_SMEM);
    cudaFuncSetAttribute(z2_kernel, cudaFuncAttributeMaxDynamicSharedMemorySize, Z2_SMEM);

    float* xu; cudaGetSymbolAddress((void**)&xu, g_xu0);
    float* cu; cudaGetSymbolAddress((void**)&cu, g_cat_u);
    float* cm; cudaGetSymbolAddress((void**)&cm, g_cat_m);
    float* au; cudaGetSymbolAddress((void**)&au, g_agg_u);
    float* am; cudaGetSymbolAddress((void**)&am, g_agg_m);
    float* hu; cudaGetSymbolAddress((void**)&hu, g_hu);
    float* hm; cudaGetSymbolAddress((void**)&hm, g_hm);
    int* adj_u; cudaGetSymbolAddress((void**)&adj_u, g_adj_u);
    int* adj_m; cudaGetSymbolAddress((void**)&adj_m, g_adj_m);
    int* off_u; cudaGetSymbolAddress((void**)&off_u, g_off_u);
    int* off_m; cudaGetSymbolAddress((void**)&off_m, g_off_m);

    zero_kernel<<<(cNU + 255) / 256, 256>>>();
    count_kernel<<<(cE + 255) / 256, 256>>>(eu, em);
    scan_kernel<<<2, 1024>>>();
    fill_kernel<<<(cE + 255) / 256, 256>>>(eu, em);
    gather_u0_kernel<<<(cNU * 16 + 255) / 256, 256>>>(n_id, user_emb);

    const int UB = (cNU + 127) / 128, MB = (cNM + 127) / 128;
    for (int i = 0; i < 3; ++i) {
        const float* xup = i ? (cu + (i - 1) * 64) : xu;
        const float* xmp = i ? (cm + (i - 1) * 64) : movie_x;
        int ldu = i ? 192 : 64, ldm = i ? 192 : 64;
        agg_mean_kernel<<<(cNM * 32 + 255) / 256, 256>>>(xup, ldu, adj_m, off_m, am, cNM);
        agg_mean_kernel<<<(cNU * 32 + 255) / 256, 256>>>(xmp, ldm, adj_u, off_u, au, cNU);
        sage_gemm_kernel<<<MB, 128, SAGE_SMEM>>>(am, xmp, ldm, Wl_um + i * 4096, Wr_um + i * 4096,
                                                 b_um + i * 64, cm + i * 64, 192, cNM);
        sage_gemm_kernel<<<UB, 128, SAGE_SMEM>>>(au, xup, ldu, Wl_mu + i * 4096, Wr_mu + i * 4096,
                                                 b_mu + i * 64, cu + i * 64, 192, cNU);
    }
    proj_gemm_kernel<<<UB, 128, PROJ_SMEM>>>(cu, proj_u_W, proj_u_b, hu, cNU);
    proj_gemm_kernel<<<MB, 128, PROJ_SMEM>>>(cm, proj_m_W, proj_m_b, hm, cNM);

    const int LB = (cEL + 127) / 128;
    z1_kernel<<<LB, 128, SAGE_SMEM>>>(lu, lm, W1, b1);
    bn_finalize_kernel<<<1, 64>>>(0, 0, 64, g1, be1, 1.f / cEL);
    z2_kernel<<<LB, 128, Z2_SMEM>>>(W2, b2);
    bn_finalize_kernel<<<1, 64>>>(128, 128, 32, g2, be2, 1.f / cEL);
    z3_kernel<<<(cEL + 255) / 256, 256>>>(W3, b3, out);
}

// round 3
// speedup vs baseline: 1.4942x; 1.4942x over previous
#include <cuda_runtime.h>
#include <cstddef>

constexpr int cNU = 100000, cNM = 20000, cH = 64, cE = 1000000, cEL = 500000;
constexpr int NBU = 98, NBM = 20;  // scan blocks (1024 elems each)

// ---- device scratch ----
__device__ float g_xu0[cNU * cH];
__device__ float g_cat_u[cNU * 192];
__device__ float g_cat_m[cNM * 192];
__device__ float g_agg_u[cNU * cH];
__device__ float g_agg_m[cNM * cH];
__device__ float g_hu[cNU * cH];   // P_u table
__device__ float g_hm[cNM * cH];   // P_m table
__device__ float g_z1[(size_t)cEL * 64];
__device__ float g_z2[(size_t)cEL * 32];
__device__ int g_cnt_u[cNU], g_cnt_m[cNM], g_pos_u[cNU], g_pos_m[cNM];
__device__ int g_off_u[cNU + 1], g_off_m[cNM + 1];
__device__ int g_adj_u[cE], g_adj_m[cE];
__device__ int g_aux[128], g_aux2[128];
__device__ double g_stats[192];
__device__ float g_bnp[192];
__device__ float g_wfu[192 * 64], g_wfm[192 * 64], g_bfu[64], g_bfm[64];

__global__ void zero_kernel() {
    int i = blockIdx.x * blockDim.x + threadIdx.x;
    if (i < cNU) { g_cnt_u[i] = 0; g_pos_u[i] = 0; }
    if (i < cNM) { g_cnt_m[i] = 0; g_pos_m[i] = 0; }
    if (i < 192) g_stats[i] = 0.0;
}

__global__ void count_kernel(const int* __restrict__ eu, const int* __restrict__ em) {
    int e = blockIdx.x * blockDim.x + threadIdx.x;
    if (e < cE) { atomicAdd(&g_cnt_u[eu[e]], 1); atomicAdd(&g_cnt_m[em[e]], 1); }
}

// phase 1: per-block exclusive scan of counts (1024 elems / block)
__global__ void __launch_bounds__(1024) scan1_kernel() {
    __shared__ int s[1024];
    int b = blockIdx.x, t = threadIdx.x;
    const int* cnt; int* off; int n, base;
    if (b < NBU) { cnt = g_cnt_u; off = g_off_u; n = cNU; base = b * 1024; }
    else         { cnt = g_cnt_m; off = g_off_m; n = cNM; base = (b - NBU) * 1024; }
    int i = base + t;
    int v = (i < n) ? cnt[i] : 0;
    int x = v;
    for (int d = 1; d < 1024; d <<= 1) {
        s[t] = x; __syncthreads();
        if (t >= d) x += s[t - d];
        __syncthreads();
    }
    if (i < n) off[i] = x - v;
    if (t == 1023) g_aux[b] = x;
}

// phase 2: scan block sums (block 0: users, block 1: movies)
__global__ void __launch_bounds__(128) scan2_kernel() {
    __shared__ int s[128];
    int t = threadIdx.x;
    int base = blockIdx.x ? NBU : 0, n = blockIdx.x ? NBM : NBU;
    int v = (t < n) ? g_aux[base + t] : 0;
    int x = v;
    for (int d = 1; d < 128; d <<= 1) {
        s[t] = x; __syncthreads();
        if (t >= d) x += s[t - d];
        __syncthreads();
    }
    if (t < n) g_aux2[base + t] = x - v;
}

// phase 3: add block offsets
__global__ void scan3_kernel() {
    int i = blockIdx.x * blockDim.x + threadIdx.x;
    if (i < cNU) g_off_u[i] += g_aux2[i >> 10];
    int j = i - cNU;
    if (j >= 0 && j < cNM) g_off_m[j] += g_aux2[NBU + (j >> 10)];
    if (i == 0) { g_off_u[cNU] = cE; g_off_m[cNM] = cE; }
}

__global__ void fill_kernel(const int* __restrict__ eu, const int* __restrict__ em) {
    int e = blockIdx.x * blockDim.x + threadIdx.x;
    if (e < cE) {
        int u = eu[e], m = em[e];
        g_adj_m[g_off_m[m] + atomicAdd(&g_pos_m[m], 1)] = u;
        g_adj_u[g_off_u[u] + atomicAdd(&g_pos_u[u], 1)] = m;
    }
}

__global__ void gather_u0_kernel(const int* __restrict__ n_id, const float* __restrict__ ue) {
    int i = blockIdx.x * blockDim.x + threadIdx.x;
    if (i < cNU * 16) {
        int r = i >> 4, c = i & 15;
        ((float4*)g_xu0)[r * 16 + c] = ((const float4*)ue)[(size_t)n_id[r] * 16 + c];
    }
}

__device__ __forceinline__ void agg_row(const float* __restrict__ src, int lds,
                                        const int* __restrict__ adj, int beg, int end,
                                        float* __restrict__ dst, int lane) {
    float ax = 0.f, ay = 0.f;
#pragma unroll 4
    for (int e = beg; e < end; ++e) {
        int s = __ldg(adj + e);
        float2 v = *(const float2*)(src + (size_t)s * lds + lane * 2);
        ax += v.x; ay += v.y;
    }
    float inv = (end > beg) ? 1.f / (float)(end - beg) : 0.f;
    *(float2*)(dst + lane * 2) = make_float2(ax * inv, ay * inv);
}

// one launch covers both directions: warps [0,cNM) -> movie dst, [cNM,cNM+cNU) -> user dst
__global__ void __launch_bounds__(256) agg_both_kernel(const float* __restrict__ xu_src, int ldu,
                                                       const float* __restrict__ xm_src, int ldm) {
    int w = (blockIdx.x * blockDim.x + threadIdx.x) >> 5;
    int lane = threadIdx.x & 31;
    if (w < cNM) {
        agg_row(xu_src, ldu, g_adj_m, g_off_m[w], g_off_m[w + 1], g_agg_m + (size_t)w * 64, lane);
    } else {
        w -= cNM;
        if (w >= cNU) return;
        agg_row(xm_src, ldm, g_adj_u, g_off_u[w], g_off_u[w + 1], g_agg_u + (size_t)w * 64, lane);
    }
}

// ---- GEMM core: 128 threads, 128-row tile ----
template <int K, int N>
__device__ __forceinline__ void gemm_compute(const float* __restrict__ sA,
                                             const float* __restrict__ sW,
                                             float acc[8][N / 8]) {
    constexpr int LDA = K + 2, CPT = N / 8;
    const int rowg = threadIdx.x & 15, colg = threadIdx.x >> 4;
    const float* aB = sA + rowg * LDA;
    const float* wB = sW + colg * CPT;
#pragma unroll 8
    for (int kk = 0; kk < K; kk += 2) {
        float2 a[8];
#pragma unroll
        for (int i = 0; i < 8; ++i) a[i] = *(const float2*)(aB + i * 16 * LDA + kk);
        float w0[CPT], w1[CPT];
#pragma unroll
        for (int j = 0; j < CPT; j += 4) {
            float4 t = *(const float4*)(wB + kk * N + j);
            w0[j] = t.x; w0[j + 1] = t.y; w0[j + 2] = t.z; w0[j + 3] = t.w;
            float4 u = *(const float4*)(wB + (kk + 1) * N + j);
            w1[j] = u.x; w1[j + 1] = u.y; w1[j + 2] = u.z; w1[j + 3] = u.w;
        }
#pragma unroll
        for (int i = 0; i < 8; ++i)
#pragma unroll
            for (int j = 0; j < CPT; ++j)
                acc[i][j] = fmaf(a[i].x, w0[j], fmaf(a[i].y, w1[j], acc[i][j]));
    }
}

constexpr int SAGE_SMEM = (128 * 130 + 128 * 64) * 4;
constexpr int PROJ_SMEM = (128 * 194 + 192 * 64) * 4;
constexpr int Z2_SMEM = (128 * 66 + 64 * 32) * 4;

// relu([agg | x] @ [Wl;Wr] + b)
__global__ void __launch_bounds__(128) sage_gemm_kernel(
    const float* __restrict__ agg, const float* __restrict__ x, int ldx,
    const float* __restrict__ Wl, const float* __restrict__ Wr,
    const float* __restrict__ bias, float* __restrict__ outp, int ldo, int nrows) {
    constexpr int LDA = 130;
    extern __shared__ float sm[];
    float* sA = sm;
    float* sW = sm + 128 * LDA;
    __shared__ float sB[64];
    const int tid = threadIdx.x, rowbase = blockIdx.x * 128;
    if (tid < 64) sB[tid] = bias[tid];
    for (int i = tid; i < 1024; i += 128) {
        ((float4*)sW)[i] = ((const float4*)Wl)[i];
        ((float4*)(sW + 4096))[i] = ((const float4*)Wr)[i];
    }
    for (int idx = tid; idx < 128 * 64; idx += 128) {
        int r = idx >> 6, c2 = idx & 63, g = rowbase + r, c = c2 * 2;
        float2 v = make_float2(0.f, 0.f);
        if (g < nrows)
            v = (c < 64) ? *(const float2*)(agg + (size_t)g * 64 + c)
                         : *(const float2*)(x + (size_t)g * ldx + (c - 64));
        *(float2*)(sA + r * LDA + c) = v;
    }
    __syncthreads();
    float acc[8][8];
#pragma unroll
    for (int i = 0; i < 8; ++i)
#pragma unroll
        for (int j = 0; j < 8; ++j) acc[i][j] = 0.f;
    gemm_compute<128, 64>(sA, sW, acc);
    const int rowg = tid & 15, colg = tid >> 4;
#pragma unroll
    for (int i = 0; i < 8; ++i) {
        int g = rowbase + rowg + 16 * i;
        if (g < nrows) {
            float o[8];
#pragma unroll
            for (int j = 0; j < 8; ++j) o[j] = fmaxf(acc[i][j] + sB[colg * 8 + j], 0.f);
            float* dst = outp + (size_t)g * ldo + colg * 8;
            *(float4*)dst = make_float4(o[0], o[1], o[2], o[3]);
            *(float4*)(dst + 4) = make_float4(o[4], o[5], o[6], o[7]);
        }
    }
}

// fuse proj and W1: Wf_u = proj_u_W @ W1[:64,:], Wf_m = proj_m_W @ W1[64:,:]
__global__ void __launch_bounds__(64) wfuse_kernel(
    const float* __restrict__ puW, const float* __restrict__ pub,
    const float* __restrict__ pmW, const float* __restrict__ pmb,
    const float* __restrict__ W1, const float* __restrict__ b1) {
    int b = blockIdx.x, c = threadIdx.x;
    if (b < 192) {
        float s = 0.f;
        for (int k = 0; k < 64; ++k) s += puW[b * 64 + k] * W1[k * 64 + c];
        g_wfu[b * 64 + c] = s;
    } else if (b < 384) {
        int r = b - 192;
        float s = 0.f;
        for (int k = 0; k < 64; ++k) s += pmW[r * 64 + k] * W1[(64 + k) * 64 + c];
        g_wfm[r * 64 + c] = s;
    } else {
        float su = 0.f, sm2 = 0.f;
        for (int k = 0; k < 64; ++k) {
            su += pub[k] * W1[k * 64 + c];
            sm2 += pmb[k] * W1[(64 + k) * 64 + c];
        }
        g_bfu[c] = su + b1[c];
        g_bfm[c] = sm2;
    }
}

// cat[*,192] @ W + b  (used for P_u, P_m tables)
__global__ void __launch_bounds__(128) proj_gemm_kernel(
    const float* __restrict__ A, const float* __restrict__ W,
    const float* __restrict__ bias, float* __restrict__ outp, int nrows) {
    constexpr int LDA = 194;
    extern __shared__ float sm[];
    float* sA = sm;
    float* sW = sm + 128 * LDA;
    __shared__ float sB[64];
    const int tid = threadIdx.x, rowbase = blockIdx.x * 128;
    if (tid < 64) sB[tid] = bias[tid];
    for (int i = tid; i < 192 * 16; i += 128) ((float4*)sW)[i] = ((const float4*)W)[i];
    for (int idx = tid; idx < 128 * 96; idx += 128) {
        int r = idx / 96, c2 = idx - r * 96, g = rowbase + r;
        float2 v = make_float2(0.f, 0.f);
        if (g < nrows) v = *(const float2*)(A + (size_t)g * 192 + c2 * 2);
        *(float2*)(sA + r * LDA + c2 * 2) = v;
    }
    __syncthreads();
    float acc[8][8];
#pragma unroll
    for (int i = 0; i < 8; ++i)
#pragma unroll
        for (int j = 0; j < 8; ++j) acc[i][j] = 0.f;
    gemm_compute<192, 64>(sA, sW, acc);
    const int rowg = tid & 15, colg = tid >> 4;
#pragma unroll
    for (int i = 0; i < 8; ++i) {
        int g = rowbase + rowg + 16 * i;
        if (g < nrows) {
            float o[8];
#pragma unroll
            for (int j = 0; j < 8; ++j) o[j] = acc[i][j] + sB[colg * 8 + j];
            float* dst = outp + (size_t)g * 64 + colg * 8;
            *(float4*)dst = make_float4(o[0], o[1], o[2], o[3]);
            *(float4*)(dst + 4) = make_float4(o[4], o[5], o[6], o[7]);
        }
    }
}

// z1[e] = P_u[lu[e]] + P_m[lm[e]]; accumulate BN1 stats
__global__ void __launch_bounds__(256) z1gather_kernel(const int* __restrict__ lu,
                                                       const int* __restrict__ lm) {
    __shared__ float sS[64], sQ[64];
    int tid = threadIdx.x;
    if (tid < 64) { sS[tid] = 0.f; sQ[tid] = 0.f; }
    __syncthreads();
    int lane = tid & 31;
    int gw = (blockIdx.x * 256 + tid) >> 5;
    int nw = gridDim.x * 8;
    float s0 = 0.f, s1 = 0.f, q0 = 0.f, q1 = 0.f;
    for (int r = gw; r < cEL; r += nw) {
        int u = __ldg(lu + r), m = __ldg(lm + r);
        float2 a = *(const float2*)(g_hu + (size_t)u * 64 + lane * 2);
        float2 b = *(const float2*)(g_hm + (size_t)m * 64 + lane * 2);
        float ox = a.x + b.x, oy = a.y + b.y;
        *(float2*)(g_z1 + (size_t)r * 64 + lane * 2) = make_float2(ox, oy);
        s0 += ox; s1 += oy; q0 += ox * ox; q1 += oy * oy;
    }
    atomicAdd(&sS[lane * 2], s0); atomicAdd(&sS[lane * 2 + 1], s1);
    atomicAdd(&sQ[lane * 2], q0); atomicAdd(&sQ[lane * 2 + 1], q1);
    __syncthreads();
    if (tid < 64) {
        atomicAdd(&g_stats[tid], (double)sS[tid]);
        atomicAdd(&g_stats[64 + tid], (double)sQ[tid]);
    }
}

__global__ void bn_finalize_kernel(int soff, int boff, int n,
                                   const float* __restrict__ gamma,
                                   const float* __restrict__ beta, float invc) {
    int t = threadIdx.x;
    if (t < n) {
        double m = g_stats[soff + t] * invc;
        double v = g_stats[soff + n + t] * invc - m * m;
        float sc = gamma[t] * rsqrtf((float)v + 1e-5f);
        g_bnp[boff + t] = sc;
        g_bnp[boff + n + t] = beta[t] - (float)m * sc;
    }
}

// z2 = bn1relu(z1) @ W2 + b2; accumulate BN2 stats
__global__ void __launch_bounds__(128) z2_kernel(const float* __restrict__ W2,
                                                 const float* __restrict__ bias) {
    constexpr int LDA = 66;
    extern __shared__ float sm[];
    float* sA = sm;
    float* sW = sm + 128 * LDA;
    __shared__ float sB[32], sSc[64], sSh[64];
    const int tid = threadIdx.x, rowbase = blockIdx.x * 128;
    if (tid < 32) sB[tid] = bias[tid];
    if (tid < 64) { sSc[tid] = g_bnp[tid]; sSh[tid] = g_bnp[64 + tid]; }
    for (int i = tid; i < 512; i += 128) ((float4*)sW)[i] = ((const float4*)W2)[i];
    __syncthreads();
    for (int idx = tid; idx < 128 * 32; idx += 128) {
        int r = idx >> 5, c2 = idx & 31, g = rowbase + r, c = c2 * 2;
        float2 v = make_float2(0.f, 0.f);
        if (g < cEL) {
            float2 z = *(const float2*)(g_z1 + (size_t)g * 64 + c);
            v.x = fmaxf(z.x * sSc[c] + sSh[c], 0.f);
            v.y = fmaxf(z.y * sSc[c + 1] + sSh[c + 1], 0.f);
        }
        *(float2*)(sA + r * LDA + c) = v;
    }
    __syncthreads();
    float acc[8][4];
#pragma unroll
    for (int i = 0; i < 8; ++i)
#pragma unroll
        for (int j = 0; j < 4; ++j) acc[i][j] = 0.f;
    gemm_compute<64, 32>(sA, sW, acc);
    const int rowg = tid & 15, colg = tid >> 4;
    float ls[4] = {0}, lq[4] = {0};
#pragma unroll
    for (int i = 0; i < 8; ++i) {
        int g = rowbase + rowg + 16 * i;
        if (g < cEL) {
            float o[4];
#pragma unroll
            for (int j = 0; j < 4; ++j) {
                o[j] = acc[i][j] + sB[colg * 4 + j];
                ls[j] += o[j]; lq[j] += o[j] * o[j];
            }
            *(float4*)(g_z2 + (size_t)g * 32 + colg * 4) = make_float4(o[0], o[1], o[2], o[3]);
        }
    }
    __syncthreads();
#pragma unroll
    for (int j = 0; j < 4; ++j) {
        sA[rowg * 32 + colg * 4 + j] = ls[j];
        sA[512 + rowg * 32 + colg * 4 + j] = lq[j];
    }
    __syncthreads();
    if (tid < 32) {
        float s = 0.f, q = 0.f;
        for (int g2 = 0; g2 < 16; ++g2) { s += sA[g2 * 32 + tid]; q += sA[512 + g2 * 32 + tid]; }
        atomicAdd(&g_stats[128 + tid], (double)s);
        atomicAdd(&g_stats[160 + tid], (double)q);
    }
}

// out = bn2relu(z2) @ W3 + b3
__global__ void __launch_bounds__(256) z3_kernel(const float* __restrict__ W3,
                                                 const float* __restrict__ b3,
                                                 float* __restrict__ out) {
    __shared__ float sW[32], sSc[32], sSh[32];
    int tid = threadIdx.x;
    if (tid < 32) { sW[tid] = W3[tid]; sSc[tid] = g_bnp[128 + tid]; sSh[tid] = g_bnp[160 + tid]; }
    __syncthreads();
    int g = blockIdx.x * 256 + tid;
    if (g < cEL) {
        const float* row = g_z2 + (size_t)g * 32;
        float acc = 0.f;
#pragma unroll
        for (int c = 0; c < 32; c += 4) {
            float4 v = *(const float4*)(row + c);
            acc += fmaxf(v.x * sSc[c] + sSh[c], 0.f) * sW[c];
            acc += fmaxf(v.y * sSc[c + 1] + sSh[c + 1], 0.f) * sW[c + 1];
            acc += fmaxf(v.z * sSc[c + 2] + sSh[c + 2], 0.f) * sW[c + 2];
            acc += fmaxf(v.w * sSc[c + 3] + sSh[c + 3], 0.f) * sW[c + 3];
        }
        out[g] = acc + b3[0];
    }
}

extern "C" void kernel_launch(void* const* d_in, const int* in_sizes, int n_in,
                              void* d_out, int out_size) {
    const int* n_id = (const int*)d_in[0];
    const float* movie_x = (const float*)d_in[1];
    const int* eu = (const int*)d_in[2];
    const int* em = (const int*)d_in[3];
    const int* lu = (const int*)d_in[4];
    const int* lm = (const int*)d_in[5];
    const float* user_emb = (const float*)d_in[6];
    const float* Wl_um = (const float*)d_in[7];
    const float* b_um = (const float*)d_in[8];
    const float* Wr_um = (const float*)d_in[9];
    const float* Wl_mu = (const float*)d_in[10];
    const float* b_mu = (const float*)d_in[11];
    const float* Wr_mu = (const float*)d_in[12];
    const float* proj_u_W = (const float*)d_in[13];
    const float* proj_u_b = (const float*)d_in[14];
    const float* proj_m_W = (const float*)d_in[15];
    const float* proj_m_b = (const float*)d_in[16];
    const float* W1 = (const float*)d_in[17];
    const float* b1 = (const float*)d_in[18];
    const float* g1 = (const float*)d_in[19];
    const float* be1 = (const float*)d_in[20];
    const float* W2 = (const float*)d_in[21];
    const float* b2 = (const float*)d_in[22];
    const float* g2 = (const float*)d_in[23];
    const float* be2 = (const float*)d_in[24];
    const float* W3 = (const float*)d_in[25];
    const float* b3 = (const float*)d_in[26];
    float* out = (float*)d_out;

    cudaFuncSetAttribute(sage_gemm_kernel, cudaFuncAttributeMaxDynamicSharedMemorySize, SAGE_SMEM);
    cudaFuncSetAttribute(proj_gemm_kernel, cudaFuncAttributeMaxDynamicSharedMemorySize, PROJ_SMEM);
    cudaFuncSetAttribute(z2_kernel, cudaFuncAttributeMaxDynamicSharedMemorySize, Z2_SMEM);

    float* xu; cudaGetSymbolAddress((void**)&xu, g_xu0);
    float* cu; cudaGetSymbolAddress((void**)&cu, g_cat_u);
    float* cm; cudaGetSymbolAddress((void**)&cm, g_cat_m);
    float* au; cudaGetSymbolAddress((void**)&au, g_agg_u);
    float* am; cudaGetSymbolAddress((void**)&am, g_agg_m);
    float* pu; cudaGetSymbolAddress((void**)&pu, g_hu);
    float* pm; cudaGetSymbolAddress((void**)&pm, g_hm);
    float* wfu; cudaGetSymbolAddress((void**)&wfu, g_wfu);
    float* wfm; cudaGetSymbolAddress((void**)&wfm, g_wfm);
    float* bfu; cudaGetSymbolAddress((void**)&bfu, g_bfu);
    float* bfm; cudaGetSymbolAddress((void**)&bfm, g_bfm);

    zero_kernel<<<(cNU + 255) / 256, 256>>>();
    count_kernel<<<(cE + 255) / 256, 256>>>(eu, em);
    scan1_kernel<<<NBU + NBM, 1024>>>();
    scan2_kernel<<<2, 128>>>();
    scan3_kernel<<<(cNU + cNM + 255) / 256, 256>>>();
    fill_kernel<<<(cE + 255) / 256, 256>>>(eu, em);
    gather_u0_kernel<<<(cNU * 16 + 255) / 256, 256>>>(n_id, user_emb);
    wfuse_kernel<<<385, 64>>>(proj_u_W, proj_u_b, proj_m_W, proj_m_b, W1, b1);

    const int UB = (cNU + 127) / 128, MB = (cNM + 127) / 128;
    const int AGGB = ((cNU + cNM) * 32 + 255) / 256;
    for (int i = 0; i < 3; ++i) {
        const float* xup = i ? (cu + (i - 1) * 64) : xu;
        const float* xmp = i ? (cm + (i - 1) * 64) : movie_x;
        int ldu = i ? 192 : 64, ldm = i ? 192 : 64;
        agg_both_kernel<<<AGGB, 256>>>(xup, ldu, xmp, ldm);
        sage_gemm_kernel<<<MB, 128, SAGE_SMEM>>>(am, xmp, ldm, Wl_um + i * 4096, Wr_um + i * 4096,
                                                 b_um + i * 64, cm + i * 64, 192, cNM);
        sage_gemm_kernel<<<UB, 128, SAGE_SMEM>>>(au, xup, ldu, Wl_mu + i * 4096, Wr_mu + i * 4096,
                                                 b_mu + i * 64, cu + i * 64, 192, cNU);
    }
    // P tables (proj ⊗ W1 fused)
    proj_gemm_kernel<<<UB, 128, PROJ_SMEM>>>(cu, wfu, bfu, pu, cNU);
    proj_gemm_kernel<<<MB, 128, PROJ_SMEM>>>(cm, wfm, bfm, pm, cNM);

    z1gather_kernel<<<1184, 256>>>(lu, lm);
    bn_finalize_kernel<<<1, 64>>>(0, 0, 64, g1, be1, 1.f / cEL);
    z2_kernel<<<(cEL + 127) / 128, 128, Z2_SMEM>>>(W2, b2);
    bn_finalize_kernel<<<1, 64>>>(128, 128, 32, g2, be2, 1.f / cEL);
    z3_kernel<<<(cEL + 255) / 256, 256>>>(W3, b3, out);
}

// round 5
// speedup vs baseline: 1.7327x; 1.1596x over previous
#include <cuda_runtime.h>
#include <cstddef>

constexpr int cNU = 100000, cNM = 20000, cH = 64, cE = 1000000, cEL = 500000;
constexpr int NBU = 98, NBM = 20;

// ---- device scratch ----
__device__ float g_xu0[cNU * cH];
__device__ float g_cat_u[cNU * 192];
__device__ float g_cat_m[cNM * 192];
__device__ float g_agg_u[cNU * cH];
__device__ float g_agg_m[cNM * cH];
__device__ float g_ym[cNM * cH];     // Y = x_m @ Wl_mu
__device__ float g_hu[cNU * cH];     // P_u
__device__ float g_hm[cNM * cH];     // P_m
__device__ float g_z2[(size_t)cEL * 32];
__device__ int g_cnt_u[cNU], g_cnt_m[cNM], g_pos_u[cNU], g_pos_m[cNM];
__device__ int g_off_u[cNU + 1], g_off_m[cNM + 1];
__device__ int g_adj_u[cE], g_adj_m[cE];
__device__ int g_aux[128], g_aux2[128];
__device__ double g_stats[192];
__device__ float g_bnp[192];
__device__ float g_wfu[192 * 64], g_wfm[192 * 64], g_bfu[64], g_bfm[64];

__global__ void zero_kernel() {
    int i = blockIdx.x * blockDim.x + threadIdx.x;
    if (i < cNU) { g_cnt_u[i] = 0; g_pos_u[i] = 0; }
    if (i < cNM) { g_cnt_m[i] = 0; g_pos_m[i] = 0; }
    if (i < 192) g_stats[i] = 0.0;
}

__global__ void count_kernel(const int* __restrict__ eu, const int* __restrict__ em) {
    int e = blockIdx.x * blockDim.x + threadIdx.x;
    if (e < cE) { atomicAdd(&g_cnt_u[eu[e]], 1); atomicAdd(&g_cnt_m[em[e]], 1); }
}

__global__ void __launch_bounds__(1024) scan1_kernel() {
    __shared__ int s[1024];
    int b = blockIdx.x, t = threadIdx.x;
    const int* cnt; int* off; int n, base;
    if (b < NBU) { cnt = g_cnt_u; off = g_off_u; n = cNU; base = b * 1024; }
    else         { cnt = g_cnt_m; off = g_off_m; n = cNM; base = (b - NBU) * 1024; }
    int i = base + t;
    int v = (i < n) ? cnt[i] : 0;
    int x = v;
    for (int d = 1; d < 1024; d <<= 1) {
        s[t] = x; __syncthreads();
        if (t >= d) x += s[t - d];
        __syncthreads();
    }
    if (i < n) off[i] = x - v;
    if (t == 1023) g_aux[b] = x;
}

__global__ void __launch_bounds__(128) scan2_kernel() {
    __shared__ int s[128];
    int t = threadIdx.x;
    int base = blockIdx.x ? NBU : 0, n = blockIdx.x ? NBM : NBU;
    int v = (t < n) ? g_aux[base + t] : 0;
    int x = v;
    for (int d = 1; d < 128; d <<= 1) {
        s[t] = x; __syncthreads();
        if (t >= d) x += s[t - d];
        __syncthreads();
    }
    if (t < n) g_aux2[base + t] = x - v;
}

__global__ void scan3_kernel() {
    int i = blockIdx.x * blockDim.x + threadIdx.x;
    if (i < cNU) g_off_u[i] += g_aux2[i >> 10];
    int j = i - cNU;
    if (j >= 0 && j < cNM) g_off_m[j] += g_aux2[NBU + (j >> 10)];
    if (i == 0) { g_off_u[cNU] = cE; g_off_m[cNM] = cE; }
}

__global__ void fill_kernel(const int* __restrict__ eu, const int* __restrict__ em) {
    int e = blockIdx.x * blockDim.x + threadIdx.x;
    if (e < cE) {
        int u = eu[e], m = em[e];
        g_adj_m[g_off_m[m] + atomicAdd(&g_pos_m[m], 1)] = u;
        g_adj_u[g_off_u[u] + atomicAdd(&g_pos_u[u], 1)] = m;
    }
}

__global__ void gather_u0_kernel(const int* __restrict__ n_id, const float* __restrict__ ue) {
    int i = blockIdx.x * blockDim.x + threadIdx.x;
    if (i < cNU * 16) {
        int r = i >> 4, c = i & 15;
        ((float4*)g_xu0)[r * 16 + c] = ((const float4*)ue)[(size_t)n_id[r] * 16 + c];
    }
}

__device__ __forceinline__ void agg_row(const float* __restrict__ src, int lds,
                                        const int* __restrict__ adj, int beg, int end,
                                        float* __restrict__ dst, int lane) {
    float ax = 0.f, ay = 0.f;
#pragma unroll 4
    for (int e = beg; e < end; ++e) {
        int s = __ldg(adj + e);
        float2 v = *(const float2*)(src + (size_t)s * lds + lane * 2);
        ax += v.x; ay += v.y;
    }
    float inv = (end > beg) ? 1.f / (float)(end - beg) : 0.f;
    *(float2*)(dst + lane * 2) = make_float2(ax * inv, ay * inv);
}

// movie-dst aggregates x_u; user-dst aggregates Y (=x_m@Wl, 64-stride)
__global__ void __launch_bounds__(256) agg_both_kernel(const float* __restrict__ xu_src, int ldu) {
    int w = (blockIdx.x * blockDim.x + threadIdx.x) >> 5;
    int lane = threadIdx.x & 31;
    if (w < cNM) {
        agg_row(xu_src, ldu, g_adj_m, g_off_m[w], g_off_m[w + 1], g_agg_m + (size_t)w * 64, lane);
    } else {
        w -= cNM;
        if (w >= cNU) return;
        agg_row(g_ym, 64, g_adj_u, g_off_u[w], g_off_u[w + 1], g_agg_u + (size_t)w * 64, lane);
    }
}

// ---- GEMM core ----
template <int K, int N>
__device__ __forceinline__ void gemm_compute(const float* __restrict__ sA,
                                             const float* __restrict__ sW,
                                             float acc[8][N / 8]) {
    constexpr int LDA = K + 2, CPT = N / 8;
    const int rowg = threadIdx.x & 15, colg = threadIdx.x >> 4;
    const float* aB = sA + rowg * LDA;
    const float* wB = sW + colg * CPT;
#pragma unroll 8
    for (int kk = 0; kk < K; kk += 2) {
        float2 a[8];
#pragma unroll
        for (int i = 0; i < 8; ++i) a[i] = *(const float2*)(aB + i * 16 * LDA + kk);
        float w0[CPT], w1[CPT];
#pragma unroll
        for (int j = 0; j < CPT; j += 4) {
            float4 t = *(const float4*)(wB + kk * N + j);
            w0[j] = t.x; w0[j + 1] = t.y; w0[j + 2] = t.z; w0[j + 3] = t.w;
            float4 u = *(const float4*)(wB + (kk + 1) * N + j);
            w1[j] = u.x; w1[j + 1] = u.y; w1[j + 2] = u.z; w1[j + 3] = u.w;
        }
#pragma unroll
        for (int i = 0; i < 8; ++i)
#pragma unroll
            for (int j = 0; j < CPT; ++j)
                acc[i][j] = fmaf(a[i].x, w0[j], fmaf(a[i].y, w1[j], acc[i][j]));
    }
}

constexpr int SAGE_SMEM = (128 * 130 + 128 * 64) * 4;
constexpr int U64_SMEM  = (128 * 66 + 64 * 64) * 4;
constexpr int PROJ_SMEM = (128 * 194 + 192 * 64) * 4;
constexpr int Z2_SMEM   = (128 * 66 + 64 * 32) * 4;

__device__ __forceinline__ void stageA64(float* sA, const float* __restrict__ x, int ldx,
                                         int rowbase, int nrows, int tid) {
    for (int idx = tid; idx < 128 * 32; idx += 128) {
        int r = idx >> 5, c2 = idx & 31, g = rowbase + r, c = c2 * 2;
        float2 v = make_float2(0.f, 0.f);
        if (g < nrows) v = *(const float2*)(x + (size_t)g * ldx + c);
        *(float2*)(sA + r * 66 + c) = v;
    }
}

// Y = x_m @ Wl (no bias/relu)
__global__ void __launch_bounds__(128) linear64_kernel(const float* __restrict__ x, int ldx,
                                                       const float* __restrict__ W,
                                                       float* __restrict__ outp, int nrows) {
    extern __shared__ float sm[];
    float* sA = sm;
    float* sW = sm + 128 * 66;
    const int tid = threadIdx.x, rowbase = blockIdx.x * 128;
    for (int i = tid; i < 1024; i += 128) ((float4*)sW)[i] = ((const float4*)W)[i];
    stageA64(sA, x, ldx, rowbase, nrows, tid);
    __syncthreads();
    float acc[8][8];
#pragma unroll
    for (int i = 0; i < 8; ++i)
#pragma unroll
        for (int j = 0; j < 8; ++j) acc[i][j] = 0.f;
    gemm_compute<64, 64>(sA, sW, acc);
    const int rowg = tid & 15, colg = tid >> 4;
#pragma unroll
    for (int i = 0; i < 8; ++i) {
        int g = rowbase + rowg + 16 * i;
        if (g < nrows) {
            float* dst = outp + (size_t)g * 64 + colg * 8;
            *(float4*)dst = make_float4(acc[i][0], acc[i][1], acc[i][2], acc[i][3]);
            *(float4*)(dst + 4) = make_float4(acc[i][4], acc[i][5], acc[i][6], acc[i][7]);
        }
    }
}

// user update: relu(x_u @ Wr + agg_u + b)  (agg_u already has Wl applied via Y)
__global__ void __launch_bounds__(128) user_sage_kernel(const float* __restrict__ x, int ldx,
                                                        const float* __restrict__ Wr,
                                                        const float* __restrict__ bias,
                                                        float* __restrict__ outp) {
    extern __shared__ float sm[];
    float* sA = sm;
    float* sW = sm + 128 * 66;
    __shared__ float sB[64];
    const int tid = threadIdx.x, rowbase = blockIdx.x * 128;
    if (tid < 64) sB[tid] = bias[tid];
    for (int i = tid; i < 1024; i += 128) ((float4*)sW)[i] = ((const float4*)Wr)[i];
    stageA64(sA, x, ldx, rowbase, cNU, tid);
    __syncthreads();
    float acc[8][8];
#pragma unroll
    for (int i = 0; i < 8; ++i)
#pragma unroll
        for (int j = 0; j < 8; ++j) acc[i][j] = 0.f;
    gemm_compute<64, 64>(sA, sW, acc);
    const int rowg = tid & 15, colg = tid >> 4;
#pragma unroll
    for (int i = 0; i < 8; ++i) {
        int g = rowbase + rowg + 16 * i;
        if (g < cNU) {
            const float* ag = g_agg_u + (size_t)g * 64 + colg * 8;
            float4 a0 = *(const float4*)ag, a1 = *(const float4*)(ag + 4);
            float o[8];
            o[0] = fmaxf(acc[i][0] + a0.x + sB[colg * 8 + 0], 0.f);
            o[1] = fmaxf(acc[i][1] + a0.y + sB[colg * 8 + 1], 0.f);
            o[2] = fmaxf(acc[i][2] + a0.z + sB[colg * 8 + 2], 0.f);
            o[3] = fmaxf(acc[i][3] + a0.w + sB[colg * 8 + 3], 0.f);
            o[4] = fmaxf(acc[i][4] + a1.x + sB[colg * 8 + 4], 0.f);
            o[5] = fmaxf(acc[i][5] + a1.y + sB[colg * 8 + 5], 0.f);
            o[6] = fmaxf(acc[i][6] + a1.z + sB[colg * 8 + 6], 0.f);
            o[7] = fmaxf(acc[i][7] + a1.w + sB[colg * 8 + 7], 0.f);
            float* dst = outp + (size_t)g * 192 + colg * 8;
            *(float4*)dst = make_float4(o[0], o[1], o[2], o[3]);
            *(float4*)(dst + 4) = make_float4(o[4], o[5], o[6], o[7]);
        }
    }
}

// movie update: relu([agg_m | x_m] @ [Wl;Wr] + b)
__global__ void __launch_bounds__(128) sage_gemm_kernel(
    const float* __restrict__ agg, const float* __restrict__ x, int ldx,
    const float* __restrict__ Wl, const float* __restrict__ Wr,
    const float* __restrict__ bias, float* __restrict__ outp, int nrows) {
    constexpr int LDA = 130;
    extern __shared__ float sm[];
    float* sA = sm;
    float* sW = sm + 128 * LDA;
    __shared__ float sB[64];
    const int tid = threadIdx.x, rowbase = blockIdx.x * 128;
    if (tid < 64) sB[tid] = bias[tid];
    for (int i = tid; i < 1024; i += 128) {
        ((float4*)sW)[i] = ((const float4*)Wl)[i];
        ((float4*)(sW + 4096))[i] = ((const float4*)Wr)[i];
    }
    for (int idx = tid; idx < 128 * 64; idx += 128) {
        int r = idx >> 6, c2 = idx & 63, g = rowbase + r, c = c2 * 2;
        float2 v = make_float2(0.f, 0.f);
        if (g < nrows)
            v = (c < 64) ? *(const float2*)(agg + (size_t)g * 64 + c)
                         : *(const float2*)(x + (size_t)g * ldx + (c - 64));
        *(float2*)(sA + r * LDA + c) = v;
    }
    __syncthreads();
    float acc[8][8];
#pragma unroll
    for (int i = 0; i < 8; ++i)
#pragma unroll
        for (int j = 0; j < 8; ++j) acc[i][j] = 0.f;
    gemm_compute<128, 64>(sA, sW, acc);
    const int rowg = tid & 15, colg = tid >> 4;
#pragma unroll
    for (int i = 0; i < 8; ++i) {
        int g = rowbase + rowg + 16 * i;
        if (g < nrows) {
            float o[8];
#pragma unroll
            for (int j = 0; j < 8; ++j) o[j] = fmaxf(acc[i][j] + sB[colg * 8 + j], 0.f);
            float* dst = outp + (size_t)g * 192 + colg * 8;
            *(float4*)dst = make_float4(o[0], o[1], o[2], o[3]);
            *(float4*)(dst + 4) = make_float4(o[4], o[5], o[6], o[7]);
        }
    }
}

__global__ void __launch_bounds__(64) wfuse_kernel(
    const float* __restrict__ puW, const float* __restrict__ pub,
    const float* __restrict__ pmW, const float* __restrict__ pmb,
    const float* __restrict__ W1, const float* __restrict__ b1) {
    int b = blockIdx.x, c = threadIdx.x;
    if (b < 192) {
        float s = 0.f;
        for (int k = 0; k < 64; ++k) s += puW[b * 64 + k] * W1[k * 64 + c];
        g_wfu[b * 64 + c] = s;
    } else if (b < 384) {
        int r = b - 192;
        float s = 0.f;
        for (int k = 0; k < 64; ++k) s += pmW[r * 64 + k] * W1[(64 + k) * 64 + c];
        g_wfm[r * 64 + c] = s;
    } else {
        float su = 0.f, sm2 = 0.f;
        for (int k = 0; k < 64; ++k) {
            su += pub[k] * W1[k * 64 + c];
            sm2 += pmb[k] * W1[(64 + k) * 64 + c];
        }
        g_bfu[c] = su + b1[c];
        g_bfm[c] = sm2;
    }
}

// combined proj: blocks [0,UB) -> users, [UB,UB+MB) -> movies
__global__ void __launch_bounds__(128) proj_gemm_kernel(int UB) {
    constexpr int LDA = 194;
    extern __shared__ float sm[];
    float* sA = sm;
    float* sW = sm + 128 * LDA;
    __shared__ float sB[64];
    const int tid = threadIdx.x;
    bool isU = (int)blockIdx.x < UB;
    const float* A = isU ? g_cat_u : g_cat_m;
    const float* W = isU ? g_wfu : g_wfm;
    const float* bias = isU ? g_bfu : g_bfm;
    float* outp = isU ? g_hu : g_hm;
    int nrows = isU ? cNU : cNM;
    int rowbase = (isU ? blockIdx.x : (blockIdx.x - UB)) * 128;
    if (tid < 64) sB[tid] = bias[tid];
    for (int i = tid; i < 192 * 16; i += 128) ((float4*)sW)[i] = ((const float4*)W)[i];
    for (int idx = tid; idx < 128 * 96; idx += 128) {
        int r = idx / 96, c2 = idx - r * 96, g = rowbase + r;
        float2 v = make_float2(0.f, 0.f);
        if (g < nrows) v = *(const float2*)(A + (size_t)g * 192 + c2 * 2);
        *(float2*)(sA + r * LDA + c2 * 2) = v;
    }
    __syncthreads();
    float acc[8][8];
#pragma unroll
    for (int i = 0; i < 8; ++i)
#pragma unroll
        for (int j = 0; j < 8; ++j) acc[i][j] = 0.f;
    gemm_compute<192, 64>(sA, sW, acc);
    const int rowg = tid & 15, colg = tid >> 4;
#pragma unroll
    for (int i = 0; i < 8; ++i) {
        int g = rowbase + rowg + 16 * i;
        if (g < nrows) {
            float o[8];
#pragma unroll
            for (int j = 0; j < 8; ++j) o[j] = acc[i][j] + sB[colg * 8 + j];
            float* dst = outp + (size_t)g * 64 + colg * 8;
            *(float4*)dst = make_float4(o[0], o[1], o[2], o[3]);
            *(float4*)(dst + 4) = make_float4(o[4], o[5], o[6], o[7]);
        }
    }
}

// BN1 stats only (no z1 store)
__global__ void __launch_bounds__(256) z1stats_kernel(const int* __restrict__ lu,
                                                      const int* __restrict__ lm) {
    __shared__ float sS[64], sQ[64];
    int tid = threadIdx.x;
    if (tid < 64) { sS[tid] = 0.f; sQ[tid] = 0.f; }
    __syncthreads();
    int lane = tid & 31;
    int gw = (blockIdx.x * 256 + tid) >> 5;
    int nw = gridDim.x * 8;
    float s0 = 0.f, s1 = 0.f, q0 = 0.f, q1 = 0.f;
    for (int r = gw; r < cEL; r += nw) {
        int u = __ldg(lu + r), m = __ldg(lm + r);
        float2 a = *(const float2*)(g_hu + (size_t)u * 64 + lane * 2);
        float2 b = *(const float2*)(g_hm + (size_t)m * 64 + lane * 2);
        float ox = a.x + b.x, oy = a.y + b.y;
        s0 += ox; s1 += oy; q0 += ox * ox; q1 += oy * oy;
    }
    atomicAdd(&sS[lane * 2], s0); atomicAdd(&sS[lane * 2 + 1], s1);
    atomicAdd(&sQ[lane * 2], q0); atomicAdd(&sQ[lane * 2 + 1], q1);
    __syncthreads();
    if (tid < 64) {
        atomicAdd(&g_stats[tid], (double)sS[tid]);
        atomicAdd(&g_stats[64 + tid], (double)sQ[tid]);
    }
}

__global__ void bn_finalize_kernel(int soff, int boff, int n,
                                   const float* __restrict__ gamma,
                                   const float* __restrict__ beta, float invc) {
    int t = threadIdx.x;
    if (t < n) {
        double m = g_stats[soff + t] * invc;
        double v = g_stats[soff + n + t] * invc - m * m;
        float sc = gamma[t] * rsqrtf((float)v + 1e-5f);
        g_bnp[boff + t] = sc;
        g_bnp[boff + n + t] = beta[t] - (float)m * sc;
    }
}

// z2 = bn1relu(P_u[lu]+P_m[lm]) @ W2 + b2; BN2 stats
__global__ void __launch_bounds__(128) z2_kernel(const int* __restrict__ lu,
                                                 const int* __restrict__ lm,
                                                 const float* __restrict__ W2,
                                                 const float* __restrict__ bias) {
    constexpr int LDA = 66;
    extern __shared__ float sm[];
    float* sA = sm;
    float* sW = sm + 128 * LDA;
    __shared__ float sB[32], sSc[64], sSh[64];
    __shared__ int sIU[128], sIM[128];
    const int tid = threadIdx.x, rowbase = blockIdx.x * 128;
    if (tid < 32) sB[tid] = bias[tid];
    if (tid < 64) { sSc[tid] = g_bnp[tid]; sSh[tid] = g_bnp[64 + tid]; }
    {
        int g = rowbase + tid;
        sIU[tid] = (g < cEL) ? __ldg(lu + g) : 0;
        sIM[tid] = (g < cEL) ? __ldg(lm + g) : 0;
    }
    for (int i = tid; i < 512; i += 128) ((float4*)sW)[i] = ((const float4*)W2)[i];
    __syncthreads();
    for (int idx = tid; idx < 128 * 32; idx += 128) {
        int r = idx >> 5, c2 = idx & 31, g = rowbase + r, c = c2 * 2;
        float2 v = make_float2(0.f, 0.f);
        if (g < cEL) {
            float2 a = *(const float2*)(g_hu + (size_t)sIU[r] * 64 + c);
            float2 b = *(const float2*)(g_hm + (size_t)sIM[r] * 64 + c);
            float zx = a.x + b.x, zy = a.y + b.y;
            v.x = fmaxf(zx * sSc[c] + sSh[c], 0.f);
            v.y = fmaxf(zy * sSc[c + 1] + sSh[c + 1], 0.f);
        }
        *(float2*)(sA + r * LDA + c) = v;
    }
    __syncthreads();
    float acc[8][4];
#pragma unroll
    for (int i = 0; i < 8; ++i)
#pragma unroll
        for (int j = 0; j < 4; ++j) acc[i][j] = 0.f;
    gemm_compute<64, 32>(sA, sW, acc);
    const int rowg = tid & 15, colg = tid >> 4;
    float ls[4] = {0}, lq[4] = {0};
#pragma unroll
    for (int i = 0; i < 8; ++i) {
        int g = rowbase + rowg + 16 * i;
        if (g < cEL) {
            float o[4];
#pragma unroll
            for (int j = 0; j < 4; ++j) {
                o[j] = acc[i][j] + sB[colg * 4 + j];
                ls[j] += o[j]; lq[j] += o[j] * o[j];
            }
            *(float4*)(g_z2 + (size_t)g * 32 + colg * 4) = make_float4(o[0], o[1], o[2], o[3]);
        }
    }
    __syncthreads();
#pragma unroll
    for (int j = 0; j < 4; ++j) {
        sA[rowg * 32 + colg * 4 + j] = ls[j];
        sA[512 + rowg * 32 + colg * 4 + j] = lq[j];
    }
    __syncthreads();
    if (tid < 32) {
        float s = 0.f, q = 0.f;
        for (int g2 = 0; g2 < 16; ++g2) { s += sA[g2 * 32 + tid]; q += sA[512 + g2 * 32 + tid]; }
        atomicAdd(&g_stats[128 + tid], (double)s);
        atomicAdd(&g_stats[160 + tid], (double)q);
    }
}

__global__ void __launch_bounds__(256) z3_kernel(const float* __restrict__ W3,
                                                 const float* __restrict__ b3,
                                                 float* __restrict__ out) {
    __shared__ float sW[32], sSc[32], sSh[32];
    int tid = threadIdx.x;
    if (tid < 32) { sW[tid] = W3[tid]; sSc[tid] = g_bnp[128 + tid]; sSh[tid] = g_bnp[160 + tid]; }
    __syncthreads();
    int g = blockIdx.x * 256 + tid;
    if (g < cEL) {
        const float* row = g_z2 + (size_t)g * 32;
        float acc = 0.f;
#pragma unroll
        for (int c = 0; c < 32; c += 4) {
            float4 v = *(const float4*)(row + c);
            acc += fmaxf(v.x * sSc[c] + sSh[c], 0.f) * sW[c];
            acc += fmaxf(v.y * sSc[c + 1] + sSh[c + 1], 0.f) * sW[c + 1];
            acc += fmaxf(v.z * sSc[c + 2] + sSh[c + 2], 0.f) * sW[c + 2];
            acc += fmaxf(v.w * sSc[c + 3] + sSh[c + 3], 0.f) * sW[c + 3];
        }
        out[g] = acc + b3[0];
    }
}

extern "C" void kernel_launch(void* const* d_in, const int* in_sizes, int n_in,
                              void* d_out, int out_size) {
    const int* n_id = (const int*)d_in[0];
    const float* movie_x = (const float*)d_in[1];
    const int* eu = (const int*)d_in[2];
    const int* em = (const int*)d_in[3];
    const int* lu = (const int*)d_in[4];
    const int* lm = (const int*)d_in[5];
    const float* user_emb = (const float*)d_in[6];
    const float* Wl_um = (const float*)d_in[7];
    const float* b_um = (const float*)d_in[8];
    const float* Wr_um = (const float*)d_in[9];
    const float* Wl_mu = (const float*)d_in[10];
    const float* b_mu = (const float*)d_in[11];
    const float* Wr_mu = (const float*)d_in[12];
    const float* proj_u_W = (const float*)d_in[13];
    const float* proj_u_b = (const float*)d_in[14];
    const float* proj_m_W = (const float*)d_in[15];
    const float* proj_m_b = (const float*)d_in[16];
    const float* W1 = (const float*)d_in[17];
    const float* b1 = (const float*)d_in[18];
    const float* g1 = (const float*)d_in[19];
    const float* be1 = (const float*)d_in[20];
    const float* W2 = (const float*)d_in[21];
    const float* b2 = (const float*)d_in[22];
    const float* g2 = (const float*)d_in[23];
    const float* be2 = (const float*)d_in[24];
    const float* W3 = (const float*)d_in[25];
    const float* b3 = (const float*)d_in[26];
    float* out = (float*)d_out;

    cudaFuncSetAttribute(sage_gemm_kernel, cudaFuncAttributeMaxDynamicSharedMemorySize, SAGE_SMEM);
    cudaFuncSetAttribute(user_sage_kernel, cudaFuncAttributeMaxDynamicSharedMemorySize, U64_SMEM);
    cudaFuncSetAttribute(linear64_kernel, cudaFuncAttributeMaxDynamicSharedMemorySize, U64_SMEM);
    cudaFuncSetAttribute(proj_gemm_kernel, cudaFuncAttributeMaxDynamicSharedMemorySize, PROJ_SMEM);
    cudaFuncSetAttribute(z2_kernel, cudaFuncAttributeMaxDynamicSharedMemorySize, Z2_SMEM);

    float* xu; cudaGetSymbolAddress((void**)&xu, g_xu0);
    float* cu; cudaGetSymbolAddress((void**)&cu, g_cat_u);
    float* cm; cudaGetSymbolAddress((void**)&cm, g_cat_m);
    float* am; cudaGetSymbolAddress((void**)&am, g_agg_m);
    float* ym; cudaGetSymbolAddress((void**)&ym, g_ym);

    zero_kernel<<<(cNU + 255) / 256, 256>>>();
    count_kernel<<<(cE + 255) / 256, 256>>>(eu, em);
    scan1_kernel<<<NBU + NBM, 1024>>>();
    scan2_kernel<<<2, 128>>>();
    scan3_kernel<<<(cNU + cNM + 255) / 256, 256>>>();
    fill_kernel<<<(cE + 255) / 256, 256>>>(eu, em);
    gather_u0_kernel<<<(cNU * 16 + 255) / 256, 256>>>(n_id, user_emb);
    wfuse_kernel<<<385, 64>>>(proj_u_W, proj_u_b, proj_m_W, proj_m_b, W1, b1);

    const int UB = (cNU + 127) / 128, MB = (cNM + 127) / 128;
    const int AGGB = ((cNU + cNM) * 32 + 255) / 256;
    for (int i = 0; i < 3; ++i) {
        const float* xup = i ? (cu + (i - 1) * 64) : xu;
        const float* xmp = i ? (cm + (i - 1) * 64) : movie_x;
        int ldu = i ? 192 : 64, ldm = i ? 192 : 64;
        linear64_kernel<<<MB, 128, U64_SMEM>>>(xmp, ldm, Wl_mu + i * 4096, ym, cNM);
        agg_both_kernel<<<AGGB, 256>>>(xup, ldu);
        sage_gemm_kernel<<<MB, 128, SAGE_SMEM>>>(am, xmp, ldm, Wl_um + i * 4096, Wr_um + i * 4096,
                                                 b_um + i * 64, cm + i * 64, cNM);
        user_sage_kernel<<<UB, 128, U64_SMEM>>>(xup, ldu, Wr_mu + i * 4096, b_mu + i * 64,
                                                cu + i * 64);
    }
    proj_gemm_kernel<<<UB + MB, 128, PROJ_SMEM>>>(UB);

    z1stats_kernel<<<1184, 256>>>(lu, lm);
    bn_finalize_kernel<<<1, 64>>>(0, 0, 64, g1, be1, 1.f / cEL);
    z2_kernel<<<(cEL + 127) / 128, 128, Z2_SMEM>>>(lu, lm, W2, b2);
    bn_finalize_kernel<<<1, 64>>>(128, 128, 32, g2, be2, 1.f / cEL);
    z3_kernel<<<(cEL + 255) / 256, 256>>>(W3, b3, out);
}

// round 7
// speedup vs baseline: 1.7431x; 1.0060x over previous
#include <cuda_runtime.h>
#include <cstddef>

constexpr int cNU = 100000, cNM = 20000, cH = 64, cE = 1000000, cEL = 500000;
constexpr int NBU = 98, NBM = 20;

// ---- device scratch ----
__device__ float g_xu0[cNU * cH];
__device__ float g_cat_u[cNU * 192];
__device__ float g_cat_m[cNM * 192];
__device__ float g_agg_u[cNU * cH];
__device__ float g_agg_m[cNM * cH];
__device__ float g_ym[cNM * cH];     // Y = x_m @ Wl_mu
__device__ float g_hu[cNU * cH];     // P_u
__device__ float g_hm[cNM * cH];     // P_m
__device__ float g_z2[(size_t)cEL * 32];
__device__ int g_cnt_u[cNU], g_cnt_m[cNM], g_pos_u[cNU], g_pos_m[cNM];
__device__ int g_off_u[cNU + 1], g_off_m[cNM + 1];
__device__ int g_adj_u[cE], g_adj_m[cE];
__device__ int g_aux[128], g_aux2[128];
__device__ double g_stats[192];
__device__ float g_bnp[192];
__device__ float g_wfu[192 * 64], g_wfm[192 * 64], g_bfu[64], g_bfm[64];

__global__ void zero_kernel() {
    int i = blockIdx.x * blockDim.x + threadIdx.x;
    if (i < cNU) { g_cnt_u[i] = 0; g_pos_u[i] = 0; }
    if (i < cNM) { g_cnt_m[i] = 0; g_pos_m[i] = 0; }
    if (i < 192) g_stats[i] = 0.0;
}

__global__ void count_kernel(const int* __restrict__ eu, const int* __restrict__ em) {
    int e = blockIdx.x * blockDim.x + threadIdx.x;
    if (e < cE) { atomicAdd(&g_cnt_u[eu[e]], 1); atomicAdd(&g_cnt_m[em[e]], 1); }
}

__global__ void __launch_bounds__(1024) scan1_kernel() {
    __shared__ int s[1024];
    int b = blockIdx.x, t = threadIdx.x;
    const int* cnt; int* off; int n, base;
    if (b < NBU) { cnt = g_cnt_u; off = g_off_u; n = cNU; base = b * 1024; }
    else         { cnt = g_cnt_m; off = g_off_m; n = cNM; base = (b - NBU) * 1024; }
    int i = base + t;
    int v = (i < n) ? cnt[i] : 0;
    int x = v;
    for (int d = 1; d < 1024; d <<= 1) {
        s[t] = x; __syncthreads();
        if (t >= d) x += s[t - d];
        __syncthreads();
    }
    if (i < n) off[i] = x - v;
    if (t == 1023) g_aux[b] = x;
}

__global__ void __launch_bounds__(128) scan2_kernel() {
    __shared__ int s[128];
    int t = threadIdx.x;
    int base = blockIdx.x ? NBU : 0, n = blockIdx.x ? NBM : NBU;
    int v = (t < n) ? g_aux[base + t] : 0;
    int x = v;
    for (int d = 1; d < 128; d <<= 1) {
        s[t] = x; __syncthreads();
        if (t >= d) x += s[t - d];
        __syncthreads();
    }
    if (t < n) g_aux2[base + t] = x - v;
}

__global__ void scan3_kernel() {
    int i = blockIdx.x * blockDim.x + threadIdx.x;
    if (i < cNU) g_off_u[i] += g_aux2[i >> 10];
    int j = i - cNU;
    if (j >= 0 && j < cNM) g_off_m[j] += g_aux2[NBU + (j >> 10)];
    if (i == 0) { g_off_u[cNU] = cE; g_off_m[cNM] = cE; }
}

__global__ void fill_kernel(const int* __restrict__ eu, const int* __restrict__ em) {
    int e = blockIdx.x * blockDim.x + threadIdx.x;
    if (e < cE) {
        int u = eu[e], m = em[e];
        g_adj_m[g_off_m[m] + atomicAdd(&g_pos_m[m], 1)] = u;
        g_adj_u[g_off_u[u] + atomicAdd(&g_pos_u[u], 1)] = m;
    }
}

__global__ void gather_u0_kernel(const int* __restrict__ n_id, const float* __restrict__ ue) {
    int i = blockIdx.x * blockDim.x + threadIdx.x;
    if (i < cNU * 16) {
        int r = i >> 4, c = i & 15;
        ((float4*)g_xu0)[r * 16 + c] = ((const float4*)ue)[(size_t)n_id[r] * 16 + c];
    }
}

__device__ __forceinline__ void agg_row(const float* __restrict__ src, int lds,
                                        const int* __restrict__ adj, int beg, int end,
                                        float* __restrict__ dst, int lane) {
    float ax = 0.f, ay = 0.f;
#pragma unroll 4
    for (int e = beg; e < end; ++e) {
        int s = __ldg(adj + e);
        float2 v = *(const float2*)(src + (size_t)s * lds + lane * 2);
        ax += v.x; ay += v.y;
    }
    float inv = (end > beg) ? 1.f / (float)(end - beg) : 0.f;
    *(float2*)(dst + lane * 2) = make_float2(ax * inv, ay * inv);
}

__global__ void __launch_bounds__(256) agg_both_kernel(const float* __restrict__ xu_src, int ldu) {
    int w = (blockIdx.x * blockDim.x + threadIdx.x) >> 5;
    int lane = threadIdx.x & 31;
    if (w < cNM) {
        agg_row(xu_src, ldu, g_adj_m, g_off_m[w], g_off_m[w + 1], g_agg_m + (size_t)w * 64, lane);
    } else {
        w -= cNM;
        if (w >= cNU) return;
        agg_row(g_ym, 64, g_adj_u, g_off_u[w], g_off_u[w + 1], g_agg_u + (size_t)w * 64, lane);
    }
}

// ---- stage weights [K][N] row-major gmem -> k-pair-interleaved float2 smem ----
// sWp[k2 * N + j] = { W[2k2][j], W[2k2+1][j] }
template <int K, int N>
__device__ __forceinline__ void stageWpair(float2* sWp, const float* __restrict__ W, int tid) {
    constexpr int NITEMS = (K / 2) * (N / 4);
    for (int idx = tid; idx < NITEMS; idx += 128) {
        int k2 = idx / (N / 4);
        int j4 = (idx - k2 * (N / 4)) * 4;
        float4 r0 = *(const float4*)(W + (size_t)(2 * k2) * N + j4);
        float4 r1 = *(const float4*)(W + (size_t)(2 * k2 + 1) * N + j4);
        float2* d = sWp + k2 * N + j4;
        d[0] = make_float2(r0.x, r1.x);
        d[1] = make_float2(r0.y, r1.y);
        d[2] = make_float2(r0.z, r1.z);
        d[3] = make_float2(r0.w, r1.w);
    }
}

// ---- GEMM core with packed fma.rn.f32x2: lanes = (even-k, odd-k) partial sums ----
template <int K, int N>
__device__ __forceinline__ void gemm_x2(const float* __restrict__ sA,
                                        const float2* __restrict__ sWp,
                                        float acc[8][N / 8]) {
    constexpr int LDA = K + 2, CPT = N / 8;
    const int rowg = threadIdx.x & 15, colg = threadIdx.x >> 4;
    const float* aB = sA + rowg * LDA;
    const float2* wB = sWp + colg * CPT;
    unsigned long long accp[8][CPT];
#pragma unroll
    for (int i = 0; i < 8; ++i)
#pragma unroll
        for (int j = 0; j < CPT; ++j) accp[i][j] = 0ull;
#pragma unroll 4
    for (int k2 = 0; k2 < K / 2; ++k2) {
        unsigned long long a[8], w[CPT];
#pragma unroll
        for (int i = 0; i < 8; ++i)
            a[i] = *(const unsigned long long*)(aB + i * 16 * LDA + k2 * 2);
#pragma unroll
        for (int j = 0; j < CPT; ++j)
            w[j] = *(const unsigned long long*)(wB + k2 * N + j);
#pragma unroll
        for (int i = 0; i < 8; ++i)
#pragma unroll
            for (int j = 0; j < CPT; ++j)
                asm("fma.rn.f32x2 %0, %1, %2, %0;" : "+l"(accp[i][j]) : "l"(a[i]), "l"(w[j]));
    }
#pragma unroll
    for (int i = 0; i < 8; ++i)
#pragma unroll
        for (int j = 0; j < CPT; ++j) {
            unsigned int lo = (unsigned int)accp[i][j];
            unsigned int hi = (unsigned int)(accp[i][j] >> 32);
            acc[i][j] = __uint_as_float(lo) + __uint_as_float(hi);
        }
}

constexpr int SAGE_SMEM = (128 * 130) * 4 + 64 * 64 * 8;
constexpr int U64_SMEM  = (128 * 66) * 4 + 32 * 64 * 8;
constexpr int PROJ_SMEM = (128 * 194) * 4 + 96 * 64 * 8;
constexpr int Z2_SMEM   = (128 * 66) * 4 + 32 * 32 * 8;

__device__ __forceinline__ void stageA64(float* sA, const float* __restrict__ x, int ldx,
                                         int rowbase, int nrows, int tid) {
    for (int idx = tid; idx < 128 * 32; idx += 128) {
        int r = idx >> 5, c2 = idx & 31, g = rowbase + r, c = c2 * 2;
        float2 v = make_float2(0.f, 0.f);
        if (g < nrows) v = *(const float2*)(x + (size_t)g * ldx + c);
        *(float2*)(sA + r * 66 + c) = v;
    }
}

// Y = x_m @ Wl (no bias/relu)
__global__ void __launch_bounds__(128) linear64_kernel(const float* __restrict__ x, int ldx,
                                                       const float* __restrict__ W,
                                                       float* __restrict__ outp, int nrows) {
    extern __shared__ float sm[];
    float* sA = sm;
    float2* sWp = (float2*)(sm + 128 * 66);
    const int tid = threadIdx.x, rowbase = blockIdx.x * 128;
    stageWpair<64, 64>(sWp, W, tid);
    stageA64(sA, x, ldx, rowbase, nrows, tid);
    __syncthreads();
    float acc[8][8];
    gemm_x2<64, 64>(sA, sWp, acc);
    const int rowg = tid & 15, colg = tid >> 4;
#pragma unroll
    for (int i = 0; i < 8; ++i) {
        int g = rowbase + rowg + 16 * i;
        if (g < nrows) {
            float* dst = outp + (size_t)g * 64 + colg * 8;
            *(float4*)dst = make_float4(acc[i][0], acc[i][1], acc[i][2], acc[i][3]);
            *(float4*)(dst + 4) = make_float4(acc[i][4], acc[i][5], acc[i][6], acc[i][7]);
        }
    }
}

// user update: relu(x_u @ Wr + agg_u + b)
__global__ void __launch_bounds__(128) user_sage_kernel(const float* __restrict__ x, int ldx,
                                                        const float* __restrict__ Wr,
                                                        const float* __restrict__ bias,
                                                        float* __restrict__ outp) {
    extern __shared__ float sm[];
    float* sA = sm;
    float2* sWp = (float2*)(sm + 128 * 66);
    __shared__ float sB[64];
    const int tid = threadIdx.x, rowbase = blockIdx.x * 128;
    if (tid < 64) sB[tid] = bias[tid];
    stageWpair<64, 64>(sWp, Wr, tid);
    stageA64(sA, x, ldx, rowbase, cNU, tid);
    __syncthreads();
    float acc[8][8];
    gemm_x2<64, 64>(sA, sWp, acc);
    const int rowg = tid & 15, colg = tid >> 4;
#pragma unroll
    for (int i = 0; i < 8; ++i) {
        int g = rowbase + rowg + 16 * i;
        if (g < cNU) {
            const float* ag = g_agg_u + (size_t)g * 64 + colg * 8;
            float4 a0 = *(const float4*)ag, a1 = *(const float4*)(ag + 4);
            float o[8];
            o[0] = fmaxf(acc[i][0] + a0.x + sB[colg * 8 + 0], 0.f);
            o[1] = fmaxf(acc[i][1] + a0.y + sB[colg * 8 + 1], 0.f);
            o[2] = fmaxf(acc[i][2] + a0.z + sB[colg * 8 + 2], 0.f);
            o[3] = fmaxf(acc[i][3] + a0.w + sB[colg * 8 + 3], 0.f);
            o[4] = fmaxf(acc[i][4] + a1.x + sB[colg * 8 + 4], 0.f);
            o[5] = fmaxf(acc[i][5] + a1.y + sB[colg * 8 + 5], 0.f);
            o[6] = fmaxf(acc[i][6] + a1.z + sB[colg * 8 + 6], 0.f);
            o[7] = fmaxf(acc[i][7] + a1.w + sB[colg * 8 + 7], 0.f);
            float* dst = outp + (size_t)g * 192 + colg * 8;
            *(float4*)dst = make_float4(o[0], o[1], o[2], o[3]);
            *(float4*)(dst + 4) = make_float4(o[4], o[5], o[6], o[7]);
        }
    }
}

// movie update: relu([agg_m | x_m] @ [Wl;Wr] + b)
__global__ void __launch_bounds__(128) sage_gemm_kernel(
    const float* __restrict__ agg, const float* __restrict__ x, int ldx,
    const float* __restrict__ Wl, const float* __restrict__ Wr,
    const float* __restrict__ bias, float* __restrict__ outp, int nrows) {
    constexpr int LDA = 130;
    extern __shared__ float sm[];
    float* sA = sm;
    float2* sWp = (float2*)(sm + 128 * LDA);
    __shared__ float sB[64];
    const int tid = threadIdx.x, rowbase = blockIdx.x * 128;
    if (tid < 64) sB[tid] = bias[tid];
    stageWpair<64, 64>(sWp, Wl, tid);             // k 0..63
    stageWpair<64, 64>(sWp + 32 * 64, Wr, tid);   // k 64..127
    for (int idx = tid; idx < 128 * 64; idx += 128) {
        int r = idx >> 6, c2 = idx & 63, g = rowbase + r, c = c2 * 2;
        float2 v = make_float2(0.f, 0.f);
        if (g < nrows)
            v = (c < 64) ? *(const float2*)(agg + (size_t)g * 64 + c)
                         : *(const float2*)(x + (size_t)g * ldx + (c - 64));
        *(float2*)(sA + r * LDA + c) = v;
    }
    __syncthreads();
    float acc[8][8];
    gemm_x2<128, 64>(sA, sWp, acc);
    const int rowg = tid & 15, colg = tid >> 4;
#pragma unroll
    for (int i = 0; i < 8; ++i) {
        int g = rowbase + rowg + 16 * i;
        if (g < nrows) {
            float o[8];
#pragma unroll
            for (int j = 0; j < 8; ++j) o[j] = fmaxf(acc[i][j] + sB[colg * 8 + j], 0.f);
            float* dst = outp + (size_t)g * 192 + colg * 8;
            *(float4*)dst = make_float4(o[0], o[1], o[2], o[3]);
            *(float4*)(dst + 4) = make_float4(o[4], o[5], o[6], o[7]);
        }
    }
}

__global__ void __launch_bounds__(64) wfuse_kernel(
    const float* __restrict__ puW, const float* __restrict__ pub,
    const float* __restrict__ pmW, const float* __restrict__ pmb,
    const float* __restrict__ W1, const float* __restrict__ b1) {
    int b = blockIdx.x, c = threadIdx.x;
    if (b < 192) {
        float s = 0.f;
        for (int k = 0; k < 64; ++k) s += puW[b * 64 + k] * W1[k * 64 + c];
        g_wfu[b * 64 + c] = s;
    } else if (b < 384) {
        int r = b - 192;
        float s = 0.f;
        for (int k = 0; k < 64; ++k) s += pmW[r * 64 + k] * W1[(64 + k) * 64 + c];
        g_wfm[r * 64 + c] = s;
    } else {
        float su = 0.f, sm2 = 0.f;
        for (int k = 0; k < 64; ++k) {
            su += pub[k] * W1[k * 64 + c];
            sm2 += pmb[k] * W1[(64 + k) * 64 + c];
        }
        g_bfu[c] = su + b1[c];
        g_bfm[c] = sm2;
    }
}

// combined proj: blocks [0,UB) -> users, [UB,UB+MB) -> movies
__global__ void __launch_bounds__(128) proj_gemm_kernel(int UB) {
    constexpr int LDA = 194;
    extern __shared__ float sm[];
    float* sA = sm;
    float2* sWp = (float2*)(sm + 128 * LDA);
    __shared__ float sB[64];
    const int tid = threadIdx.x;
    bool isU = (int)blockIdx.x < UB;
    const float* A = isU ? g_cat_u : g_cat_m;
    const float* W = isU ? g_wfu : g_wfm;
    const float* bias = isU ? g_bfu : g_bfm;
    float* outp = isU ? g_hu : g_hm;
    int nrows = isU ? cNU : cNM;
    int rowbase = (isU ? blockIdx.x : (blockIdx.x - UB)) * 128;
    if (tid < 64) sB[tid] = bias[tid];
    stageWpair<192, 64>(sWp, W, tid);
    for (int idx = tid; idx < 128 * 96; idx += 128) {
        int r = idx / 96, c2 = idx - r * 96, g = rowbase + r;
        float2 v = make_float2(0.f, 0.f);
        if (g < nrows) v = *(const float2*)(A + (size_t)g * 192 + c2 * 2);
        *(float2*)(sA + r * LDA + c2 * 2) = v;
    }
    __syncthreads();
    float acc[8][8];
    gemm_x2<192, 64>(sA, sWp, acc);
    const int rowg = tid & 15, colg = tid >> 4;
#pragma unroll
    for (int i = 0; i < 8; ++i) {
        int g = rowbase + rowg + 16 * i;
        if (g < nrows) {
            float o[8];
#pragma unroll
            for (int j = 0; j < 8; ++j) o[j] = acc[i][j] + sB[colg * 8 + j];
            float* dst = outp + (size_t)g * 64 + colg * 8;
            *(float4*)dst = make_float4(o[0], o[1], o[2], o[3]);
            *(float4*)(dst + 4) = make_float4(o[4], o[5], o[6], o[7]);
        }
    }
}

// BN1 stats only (no z1 store)
__global__ void __launch_bounds__(256) z1stats_kernel(const int* __restrict__ lu,
                                                      const int* __restrict__ lm) {
    __shared__ float sS[64], sQ[64];
    int tid = threadIdx.x;
    if (tid < 64) { sS[tid] = 0.f; sQ[tid] = 0.f; }
    __syncthreads();
    int lane = tid & 31;
    int gw = (blockIdx.x * 256 + tid) >> 5;
    int nw = gridDim.x * 8;
    float s0 = 0.f, s1 = 0.f, q0 = 0.f, q1 = 0.f;
    for (int r = gw; r < cEL; r += nw) {
        int u = __ldg(lu + r), m = __ldg(lm + r);
        float2 a = *(const float2*)(g_hu + (size_t)u * 64 + lane * 2);
        float2 b = *(const float2*)(g_hm + (size_t)m * 64 + lane * 2);
        float ox = a.x + b.x, oy = a.y + b.y;
        s0 += ox; s1 += oy; q0 += ox * ox; q1 += oy * oy;
    }
    atomicAdd(&sS[lane * 2], s0); atomicAdd(&sS[lane * 2 + 1], s1);
    atomicAdd(&sQ[lane * 2], q0); atomicAdd(&sQ[lane * 2 + 1], q1);
    __syncthreads();
    if (tid < 64) {
        atomicAdd(&g_stats[tid], (double)sS[tid]);
        atomicAdd(&g_stats[64 + tid], (double)sQ[tid]);
    }
}

__global__ void bn_finalize_kernel(int soff, int boff, int n,
                                   const float* __restrict__ gamma,
                                   const float* __restrict__ beta, float invc) {
    int t = threadIdx.x;
    if (t < n) {
        double m = g_stats[soff + t] * invc;
        double v = g_stats[soff + n + t] * invc - m * m;
        float sc = gamma[t] * rsqrtf((float)v + 1e-5f);
        g_bnp[boff + t] = sc;
        g_bnp[boff + n + t] = beta[t] - (float)m * sc;
    }
}

// z2 = bn1relu(P_u[lu]+P_m[lm]) @ W2 + b2; BN2 stats
__global__ void __launch_bounds__(128) z2_kernel(const int* __restrict__ lu,
                                                 const int* __restrict__ lm,
                                                 const float* __restrict__ W2,
                                                 const float* __restrict__ bias) {
    constexpr int LDA = 66;
    extern __shared__ float sm[];
    float* sA = sm;
    float2* sWp = (float2*)(sm + 128 * LDA);
    __shared__ float sB[32], sSc[64], sSh[64];
    __shared__ int sIU[128], sIM[128];
    const int tid = threadIdx.x, rowbase = blockIdx.x * 128;
    if (tid < 32) sB[tid] = bias[tid];
    if (tid < 64) { sSc[tid] = g_bnp[tid]; sSh[tid] = g_bnp[64 + tid]; }
    {
        int g = rowbase + tid;
        sIU[tid] = (g < cEL) ? __ldg(lu + g) : 0;
        sIM[tid] = (g < cEL) ? __ldg(lm + g) : 0;
    }
    stageWpair<64, 32>(sWp, W2, tid);
    __syncthreads();
    for (int idx = tid; idx < 128 * 32; idx += 128) {
        int r = idx >> 5, c2 = idx & 31, g = rowbase + r, c = c2 * 2;
        float2 v = make_float2(0.f, 0.f);
        if (g < cEL) {
            float2 a = *(const float2*)(g_hu + (size_t)sIU[r] * 64 + c);
            float2 b = *(const float2*)(g_hm + (size_t)sIM[r] * 64 + c);
            float zx = a.x + b.x, zy = a.y + b.y;
            v.x = fmaxf(zx * sSc[c] + sSh[c], 0.f);
            v.y = fmaxf(zy * sSc[c + 1] + sSh[c + 1], 0.f);
        }
        *(float2*)(sA + r * LDA + c) = v;
    }
    __syncthreads();
    float acc[8][4];
    gemm_x2<64, 32>(sA, sWp, acc);
    const int rowg = tid & 15, colg = tid >> 4;
    float ls[4] = {0}, lq[4] = {0};
#pragma unroll
    for (int i = 0; i < 8; ++i) {
        int g = rowbase + rowg + 16 * i;
        if (g < cEL) {
            float o[4];
#pragma unroll
            for (int j = 0; j < 4; ++j) {
                o[j] = acc[i][j] + sB[colg * 4 + j];
                ls[j] += o[j]; lq[j] += o[j] * o[j];
            }
            *(float4*)(g_z2 + (size_t)g * 32 + colg * 4) = make_float4(o[0], o[1], o[2], o[3]);
        }
    }
    __syncthreads();
#pragma unroll
    for (int j = 0; j < 4; ++j) {
        sA[rowg * 32 + colg * 4 + j] = ls[j];
        sA[512 + rowg * 32 + colg * 4 + j] = lq[j];
    }
    __syncthreads();
    if (tid < 32) {
        float s = 0.f, q = 0.f;
        for (int g2 = 0; g2 < 16; ++g2) { s += sA[g2 * 32 + tid]; q += sA[512 + g2 * 32 + tid]; }
        atomicAdd(&g_stats[128 + tid], (double)s);
        atomicAdd(&g_stats[160 + tid], (double)q);
    }
}

__global__ void __launch_bounds__(256) z3_kernel(const float* __restrict__ W3,
                                                 const float* __restrict__ b3,
                                                 float* __restrict__ out) {
    __shared__ float sW[32], sSc[32], sSh[32];
    int tid = threadIdx.x;
    if (tid < 32) { sW[tid] = W3[tid]; sSc[tid] = g_bnp[128 + tid]; sSh[tid] = g_bnp[160 + tid]; }
    __syncthreads();
    int g = blockIdx.x * 256 + tid;
    if (g < cEL) {
        const float* row = g_z2 + (size_t)g * 32;
        float acc = 0.f;
#pragma unroll
        for (int c = 0; c < 32; c += 4) {
            float4 v = *(const float4*)(row + c);
            acc += fmaxf(v.x * sSc[c] + sSh[c], 0.f) * sW[c];
            acc += fmaxf(v.y * sSc[c + 1] + sSh[c + 1], 0.f) * sW[c + 1];
            acc += fmaxf(v.z * sSc[c + 2] + sSh[c + 2], 0.f) * sW[c + 2];
            acc += fmaxf(v.w * sSc[c + 3] + sSh[c + 3], 0.f) * sW[c + 3];
        }
        out[g] = acc + b3[0];
    }
}

extern "C" void kernel_launch(void* const* d_in, const int* in_sizes, int n_in,
                              void* d_out, int out_size) {
    const int* n_id = (const int*)d_in[0];
    const float* movie_x = (const float*)d_in[1];
    const int* eu = (const int*)d_in[2];
    const int* em = (const int*)d_in[3];
    const int* lu = (const int*)d_in[4];
    const int* lm = (const int*)d_in[5];
    const float* user_emb = (const float*)d_in[6];
    const float* Wl_um = (const float*)d_in[7];
    const float* b_um = (const float*)d_in[8];
    const float* Wr_um = (const float*)d_in[9];
    const float* Wl_mu = (const float*)d_in[10];
    const float* b_mu = (const float*)d_in[11];
    const float* Wr_mu = (const float*)d_in[12];
    const float* proj_u_W = (const float*)d_in[13];
    const float* proj_u_b = (const float*)d_in[14];
    const float* proj_m_W = (const float*)d_in[15];
    const float* proj_m_b = (const float*)d_in[16];
    const float* W1 = (const float*)d_in[17];
    const float* b1 = (const float*)d_in[18];
    const float* g1 = (const float*)d_in[19];
    const float* be1 = (const float*)d_in[20];
    const float* W2 = (const float*)d_in[21];
    const float* b2 = (const float*)d_in[22];
    const float* g2 = (const float*)d_in[23];
    const float* be2 = (const float*)d_in[24];
    const float* W3 = (const float*)d_in[25];
    const float* b3 = (const float*)d_in[26];
    float* out = (float*)d_out;

    cudaFuncSetAttribute(sage_gemm_kernel, cudaFuncAttributeMaxDynamicSharedMemorySize, SAGE_SMEM);
    cudaFuncSetAttribute(user_sage_kernel, cudaFuncAttributeMaxDynamicSharedMemorySize, U64_SMEM);
    cudaFuncSetAttribute(linear64_kernel, cudaFuncAttributeMaxDynamicSharedMemorySize, U64_SMEM);
    cudaFuncSetAttribute(proj_gemm_kernel, cudaFuncAttributeMaxDynamicSharedMemorySize, PROJ_SMEM);
    cudaFuncSetAttribute(z2_kernel, cudaFuncAttributeMaxDynamicSharedMemorySize, Z2_SMEM);

    float* xu; cudaGetSymbolAddress((void**)&xu, g_xu0);
    float* cu; cudaGetSymbolAddress((void**)&cu, g_cat_u);
    float* cm; cudaGetSymbolAddress((void**)&cm, g_cat_m);
    float* am; cudaGetSymbolAddress((void**)&am, g_agg_m);
    float* ym; cudaGetSymbolAddress((void**)&ym, g_ym);

    zero_kernel<<<(cNU + 255) / 256, 256>>>();
    count_kernel<<<(cE + 255) / 256, 256>>>(eu, em);
    scan1_kernel<<<NBU + NBM, 1024>>>();
    scan2_kernel<<<2, 128>>>();
    scan3_kernel<<<(cNU + cNM + 255) / 256, 256>>>();
    fill_kernel<<<(cE + 255) / 256, 256>>>(eu, em);
    gather_u0_kernel<<<(cNU * 16 + 255) / 256, 256>>>(n_id, user_emb);
    wfuse_kernel<<<385, 64>>>(proj_u_W, proj_u_b, proj_m_W, proj_m_b, W1, b1);

    const int UB = (cNU + 127) / 128, MB = (cNM + 127) / 128;
    const int AGGB = ((cNU + cNM) * 32 + 255) / 256;
    for (int i = 0; i < 3; ++i) {
        const float* xup = i ? (cu + (i - 1) * 64) : xu;
        const float* xmp = i ? (cm + (i - 1) * 64) : movie_x;
        int ldu = i ? 192 : 64, ldm = i ? 192 : 64;
        linear64_kernel<<<MB, 128, U64_SMEM>>>(xmp, ldm, Wl_mu + i * 4096, ym, cNM);
        agg_both_kernel<<<AGGB, 256>>>(xup, ldu);
        sage_gemm_kernel<<<MB, 128, SAGE_SMEM>>>(am, xmp, ldm, Wl_um + i * 4096, Wr_um + i * 4096,
                                                 b_um + i * 64, cm + i * 64, cNM);
        user_sage_kernel<<<UB, 128, U64_SMEM>>>(xup, ldu, Wr_mu + i * 4096, b_mu + i * 64,
                                                cu + i * 64);
    }
    proj_gemm_kernel<<<UB + MB, 128, PROJ_SMEM>>>(UB);

    z1stats_kernel<<<1184, 256>>>(lu, lm);
    bn_finalize_kernel<<<1, 64>>>(0, 0, 64, g1, be1, 1.f / cEL);
    z2_kernel<<<(cEL + 127) / 128, 128, Z2_SMEM>>>(lu, lm, W2, b2);
    bn_finalize_kernel<<<1, 64>>>(128, 128, 32, g2, be2, 1.f / cEL);
    z3_kernel<<<(cEL + 255) / 256, 256>>>(W3, b3, out);
}

// round 9
// speedup vs baseline: 1.8756x; 1.0760x over previous
#include <cuda_runtime.h>
#include <cstddef>

constexpr int cNU = 100000, cNM = 20000, cH = 64, cE = 1000000, cEL = 500000;
constexpr int NBU = 98, NBM = 20;

// ---- device scratch ----
__device__ float g_xu0[cNU * cH];
__device__ float g_cat_u[cNU * 192];
__device__ float g_cat_m[cNM * 192];
__device__ float g_agg_u[cNU * cH];
__device__ float g_agg_m[cNM * cH];
__device__ float g_ym[cNM * cH];     // Y = x_m @ Wl_mu
__device__ float g_hu[cNU * cH];     // P_u
__device__ float g_hm[cNM * cH];     // P_m
__device__ float g_z2[(size_t)cEL * 32];
__device__ int g_cnt_u[cNU], g_cnt_m[cNM], g_pos_u[cNU], g_pos_m[cNM];
__device__ int g_off_u[cNU + 1], g_off_m[cNM + 1];
__device__ int g_adj_u[cE], g_adj_m[cE];
__device__ int g_aux[128], g_aux2[128];
__device__ double g_stats[192];
__device__ float g_bnp[192];
__device__ float g_wfu[192 * 64], g_wfm[192 * 64], g_bfu[64], g_bfm[64];

__global__ void zero_kernel() {
    int i = blockIdx.x * blockDim.x + threadIdx.x;
    if (i < cNU) { g_cnt_u[i] = 0; g_pos_u[i] = 0; }
    if (i < cNM) { g_cnt_m[i] = 0; g_pos_m[i] = 0; }
    if (i < 192) g_stats[i] = 0.0;
}

__global__ void count_kernel(const int* __restrict__ eu, const int* __restrict__ em) {
    int e = blockIdx.x * blockDim.x + threadIdx.x;
    if (e < cE) { atomicAdd(&g_cnt_u[eu[e]], 1); atomicAdd(&g_cnt_m[em[e]], 1); }
}

__global__ void __launch_bounds__(1024) scan1_kernel() {
    __shared__ int s[1024];
    int b = blockIdx.x, t = threadIdx.x;
    const int* cnt; int* off; int n, base;
    if (b < NBU) { cnt = g_cnt_u; off = g_off_u; n = cNU; base = b * 1024; }
    else         { cnt = g_cnt_m; off = g_off_m; n = cNM; base = (b - NBU) * 1024; }
    int i = base + t;
    int v = (i < n) ? cnt[i] : 0;
    int x = v;
    for (int d = 1; d < 1024; d <<= 1) {
        s[t] = x; __syncthreads();
        if (t >= d) x += s[t - d];
        __syncthreads();
    }
    if (i < n) off[i] = x - v;
    if (t == 1023) g_aux[b] = x;
}

__global__ void __launch_bounds__(128) scan2_kernel() {
    __shared__ int s[128];
    int t = threadIdx.x;
    int base = blockIdx.x ? NBU : 0, n = blockIdx.x ? NBM : NBU;
    int v = (t < n) ? g_aux[base + t] : 0;
    int x = v;
    for (int d = 1; d < 128; d <<= 1) {
        s[t] = x; __syncthreads();
        if (t >= d) x += s[t - d];
        __syncthreads();
    }
    if (t < n) g_aux2[base + t] = x - v;
}

__global__ void scan3_kernel() {
    int i = blockIdx.x * blockDim.x + threadIdx.x;
    if (i < cNU) g_off_u[i] += g_aux2[i >> 10];
    int j = i - cNU;
    if (j >= 0 && j < cNM) g_off_m[j] += g_aux2[NBU + (j >> 10)];
    if (i == 0) { g_off_u[cNU] = cE; g_off_m[cNM] = cE; }
}

__global__ void fill_kernel(const int* __restrict__ eu, const int* __restrict__ em) {
    int e = blockIdx.x * blockDim.x + threadIdx.x;
    if (e < cE) {
        int u = eu[e], m = em[e];
        g_adj_m[g_off_m[m] + atomicAdd(&g_pos_m[m], 1)] = u;
        g_adj_u[g_off_u[u] + atomicAdd(&g_pos_u[u], 1)] = m;
    }
}

__global__ void gather_u0_kernel(const int* __restrict__ n_id, const float* __restrict__ ue) {
    int i = blockIdx.x * blockDim.x + threadIdx.x;
    if (i < cNU * 16) {
        int r = i >> 4, c = i & 15;
        ((float4*)g_xu0)[r * 16 + c] = ((const float4*)ue)[(size_t)n_id[r] * 16 + c];
    }
}

__device__ __forceinline__ void agg_row(const float* __restrict__ src, int lds,
                                        const int* __restrict__ adj, int beg, int end,
                                        float* __restrict__ dst, int lane) {
    float ax = 0.f, ay = 0.f;
#pragma unroll 4
    for (int e = beg; e < end; ++e) {
        int s = __ldg(adj + e);
        float2 v = *(const float2*)(src + (size_t)s * lds + lane * 2);
        ax += v.x; ay += v.y;
    }
    float inv = (end > beg) ? 1.f / (float)(end - beg) : 0.f;
    *(float2*)(dst + lane * 2) = make_float2(ax * inv, ay * inv);
}

__global__ void __launch_bounds__(256) agg_both_kernel(const float* __restrict__ xu_src, int ldu) {
    int w = (blockIdx.x * blockDim.x + threadIdx.x) >> 5;
    int lane = threadIdx.x & 31;
    if (w < cNM) {
        agg_row(xu_src, ldu, g_adj_m, g_off_m[w], g_off_m[w + 1], g_agg_m + (size_t)w * 64, lane);
    } else {
        w -= cNM;
        if (w >= cNU) return;
        agg_row(g_ym, 64, g_adj_u, g_off_u[w], g_off_u[w + 1], g_agg_u + (size_t)w * 64, lane);
    }
}

// ---- stage weights [K][N] row-major gmem -> k-pair-interleaved float2 smem ----
template <int K, int N>
__device__ __forceinline__ void stageWpair(float2* sWp, const float* __restrict__ W, int tid) {
    constexpr int NITEMS = (K / 2) * (N / 4);
    for (int idx = tid; idx < NITEMS; idx += 256) {
        int k2 = idx / (N / 4);
        int j4 = (idx - k2 * (N / 4)) * 4;
        float4 r0 = *(const float4*)(W + (size_t)(2 * k2) * N + j4);
        float4 r1 = *(const float4*)(W + (size_t)(2 * k2 + 1) * N + j4);
        float2* d = sWp + k2 * N + j4;
        d[0] = make_float2(r0.x, r1.x);
        d[1] = make_float2(r0.y, r1.y);
        d[2] = make_float2(r0.z, r1.z);
        d[3] = make_float2(r0.w, r1.w);
    }
}

// ---- GEMM core, 256 threads: thread (rowg=tid&31, colg=tid>>5) owns rows rowg+32i (i<4),
// cols colg*CPT..; W reads are warp-uniform (broadcast), A reads conflict-free ----
template <int K, int N>
__device__ __forceinline__ void gemm_x2(const float* __restrict__ sA,
                                        const float2* __restrict__ sWp,
                                        float acc[4][N / 8]) {
    constexpr int LDA = K + 2, CPT = N / 8;
    const int rowg = threadIdx.x & 31, colg = threadIdx.x >> 5;
    const float* aB = sA + rowg * LDA;
    const float2* wB = sWp + colg * CPT;
    unsigned long long accp[4][CPT];
#pragma unroll
    for (int i = 0; i < 4; ++i)
#pragma unroll
        for (int j = 0; j < CPT; ++j) accp[i][j] = 0ull;
#pragma unroll 4
    for (int k2 = 0; k2 < K / 2; ++k2) {
        unsigned long long a[4], w[CPT];
#pragma unroll
        for (int i = 0; i < 4; ++i)
            a[i] = *(const unsigned long long*)(aB + i * 32 * LDA + k2 * 2);
#pragma unroll
        for (int j = 0; j < CPT; ++j)
            w[j] = *(const unsigned long long*)(wB + k2 * N + j);
#pragma unroll
        for (int i = 0; i < 4; ++i)
#pragma unroll
            for (int j = 0; j < CPT; ++j)
                asm("fma.rn.f32x2 %0, %1, %2, %0;" : "+l"(accp[i][j]) : "l"(a[i]), "l"(w[j]));
    }
#pragma unroll
    for (int i = 0; i < 4; ++i)
#pragma unroll
        for (int j = 0; j < CPT; ++j) {
            unsigned int lo = (unsigned int)accp[i][j];
            unsigned int hi = (unsigned int)(accp[i][j] >> 32);
            acc[i][j] = __uint_as_float(lo) + __uint_as_float(hi);
        }
}

constexpr int SAGE_SMEM = (128 * 130) * 4 + 64 * 64 * 8;   // 99328
constexpr int U64_SMEM  = (128 * 66) * 4 + 32 * 64 * 8;    // 50176 -> 2 CTAs/SM
constexpr int PROJ_SMEM = (128 * 194) * 4 + 96 * 64 * 8;   // 148480
constexpr int Z2_SMEM   = (128 * 66) * 4 + 32 * 32 * 8;    // 41984 -> 2 CTAs/SM

__device__ __forceinline__ void stageA64(float* sA, const float* __restrict__ x, int ldx,
                                         int rowbase, int nrows, int tid) {
    for (int idx = tid; idx < 128 * 32; idx += 256) {
        int r = idx >> 5, c2 = idx & 31, g = rowbase + r, c = c2 * 2;
        float2 v = make_float2(0.f, 0.f);
        if (g < nrows) v = *(const float2*)(x + (size_t)g * ldx + c);
        *(float2*)(sA + r * 66 + c) = v;
    }
}

// Y = x_m @ Wl (no bias/relu)
__global__ void __launch_bounds__(256) linear64_kernel(const float* __restrict__ x, int ldx,
                                                       const float* __restrict__ W,
                                                       float* __restrict__ outp, int nrows) {
    extern __shared__ float sm[];
    float* sA = sm;
    float2* sWp = (float2*)(sm + 128 * 66);
    const int tid = threadIdx.x, rowbase = blockIdx.x * 128;
    stageWpair<64, 64>(sWp, W, tid);
    stageA64(sA, x, ldx, rowbase, nrows, tid);
    __syncthreads();
    float acc[4][8];
    gemm_x2<64, 64>(sA, sWp, acc);
    const int rowg = tid & 31, colg = tid >> 5;
#pragma unroll
    for (int i = 0; i < 4; ++i) {
        int g = rowbase + rowg + 32 * i;
        if (g < nrows) {
            float* dst = outp + (size_t)g * 64 + colg * 8;
            *(float4*)dst = make_float4(acc[i][0], acc[i][1], acc[i][2], acc[i][3]);
            *(float4*)(dst + 4) = make_float4(acc[i][4], acc[i][5], acc[i][6], acc[i][7]);
        }
    }
}

// user update: relu(x_u @ Wr + agg_u + b)
__global__ void __launch_bounds__(256) user_sage_kernel(const float* __restrict__ x, int ldx,
                                                        const float* __restrict__ Wr,
                                                        const float* __restrict__ bias,
                                                        float* __restrict__ outp) {
    extern __shared__ float sm[];
    float* sA = sm;
    float2* sWp = (float2*)(sm + 128 * 66);
    __shared__ float sB[64];
    const int tid = threadIdx.x, rowbase = blockIdx.x * 128;
    if (tid < 64) sB[tid] = bias[tid];
    stageWpair<64, 64>(sWp, Wr, tid);
    stageA64(sA, x, ldx, rowbase, cNU, tid);
    __syncthreads();
    float acc[4][8];
    gemm_x2<64, 64>(sA, sWp, acc);
    const int rowg = tid & 31, colg = tid >> 5;
#pragma unroll
    for (int i = 0; i < 4; ++i) {
        int g = rowbase + rowg + 32 * i;
        if (g < cNU) {
            const float* ag = g_agg_u + (size_t)g * 64 + colg * 8;
            float4 a0 = *(const float4*)ag, a1 = *(const float4*)(ag + 4);
            float o[8];
            o[0] = fmaxf(acc[i][0] + a0.x + sB[colg * 8 + 0], 0.f);
            o[1] = fmaxf(acc[i][1] + a0.y + sB[colg * 8 + 1], 0.f);
            o[2] = fmaxf(acc[i][2] + a0.z + sB[colg * 8 + 2], 0.f);
            o[3] = fmaxf(acc[i][3] + a0.w + sB[colg * 8 + 3], 0.f);
            o[4] = fmaxf(acc[i][4] + a1.x + sB[colg * 8 + 4], 0.f);
            o[5] = fmaxf(acc[i][5] + a1.y + sB[colg * 8 + 5], 0.f);
            o[6] = fmaxf(acc[i][6] + a1.z + sB[colg * 8 + 6], 0.f);
            o[7] = fmaxf(acc[i][7] + a1.w + sB[colg * 8 + 7], 0.f);
            float* dst = outp + (size_t)g * 192 + colg * 8;
            *(float4*)dst = make_float4(o[0], o[1], o[2], o[3]);
            *(float4*)(dst + 4) = make_float4(o[4], o[5], o[6], o[7]);
        }
    }
}

// movie update: relu([agg_m | x_m] @ [Wl;Wr] + b)
__global__ void __launch_bounds__(256) sage_gemm_kernel(
    const float* __restrict__ agg, const float* __restrict__ x, int ldx,
    const float* __restrict__ Wl, const float* __restrict__ Wr,
    const float* __restrict__ bias, float* __restrict__ outp, int nrows) {
    constexpr int LDA = 130;
    extern __shared__ float sm[];
    float* sA = sm;
    float2* sWp = (float2*)(sm + 128 * LDA);
    __shared__ float sB[64];
    const int tid = threadIdx.x, rowbase = blockIdx.x * 128;
    if (tid < 64) sB[tid] = bias[tid];
    stageWpair<64, 64>(sWp, Wl, tid);             // k 0..63
    stageWpair<64, 64>(sWp + 32 * 64, Wr, tid);   // k 64..127
    for (int idx = tid; idx < 128 * 64; idx += 256) {
        int r = idx >> 6, c2 = idx & 63, g = rowbase + r, c = c2 * 2;
        float2 v = make_float2(0.f, 0.f);
        if (g < nrows)
            v = (c < 64) ? *(const float2*)(agg + (size_t)g * 64 + c)
                         : *(const float2*)(x + (size_t)g * ldx + (c - 64));
        *(float2*)(sA + r * LDA + c) = v;
    }
    __syncthreads();
    float acc[4][8];
    gemm_x2<128, 64>(sA, sWp, acc);
    const int rowg = tid & 31, colg = tid >> 5;
#pragma unroll
    for (int i = 0; i < 4; ++i) {
        int g = rowbase + rowg + 32 * i;
        if (g < nrows) {
            float o[8];
#pragma unroll
            for (int j = 0; j < 8; ++j) o[j] = fmaxf(acc[i][j] + sB[colg * 8 + j], 0.f);
            float* dst = outp + (size_t)g * 192 + colg * 8;
            *(float4*)dst = make_float4(o[0], o[1], o[2], o[3]);
            *(float4*)(dst + 4) = make_float4(o[4], o[5], o[6], o[7]);
        }
    }
}

__global__ void __launch_bounds__(64) wfuse_kernel(
    const float* __restrict__ puW, const float* __restrict__ pub,
    const float* __restrict__ pmW, const float* __restrict__ pmb,
    const float* __restrict__ W1, const float* __restrict__ b1) {
    int b = blockIdx.x, c = threadIdx.x;
    if (b < 192) {
        float s = 0.f;
        for (int k = 0; k < 64; ++k) s += puW[b * 64 + k] * W1[k * 64 + c];
        g_wfu[b * 64 + c] = s;
    } else if (b < 384) {
        int r = b - 192;
        float s = 0.f;
        for (int k = 0; k < 64; ++k) s += pmW[r * 64 + k] * W1[(64 + k) * 64 + c];
        g_wfm[r * 64 + c] = s;
    } else {
        float su = 0.f, sm2 = 0.f;
        for (int k = 0; k < 64; ++k) {
            su += pub[k] * W1[k * 64 + c];
            sm2 += pmb[k] * W1[(64 + k) * 64 + c];
        }
        g_bfu[c] = su + b1[c];
        g_bfm[c] = sm2;
    }
}

// combined proj: blocks [0,UB) -> users, [UB,UB+MB) -> movies
__global__ void __launch_bounds__(256) proj_gemm_kernel(int UB) {
    constexpr int LDA = 194;
    extern __shared__ float sm[];
    float* sA = sm;
    float2* sWp = (float2*)(sm + 128 * LDA);
    __shared__ float sB[64];
    const int tid = threadIdx.x;
    bool isU = (int)blockIdx.x < UB;
    const float* A = isU ? g_cat_u : g_cat_m;
    const float* W = isU ? g_wfu : g_wfm;
    const float* bias = isU ? g_bfu : g_bfm;
    float* outp = isU ? g_hu : g_hm;
    int nrows = isU ? cNU : cNM;
    int rowbase = (isU ? blockIdx.x : (blockIdx.x - UB)) * 128;
    if (tid < 64) sB[tid] = bias[tid];
    stageWpair<192, 64>(sWp, W, tid);
    for (int idx = tid; idx < 128 * 96; idx += 256) {
        int r = idx / 96, c2 = idx - r * 96, g = rowbase + r;
        float2 v = make_float2(0.f, 0.f);
        if (g < nrows) v = *(const float2*)(A + (size_t)g * 192 + c2 * 2);
        *(float2*)(sA + r * LDA + c2 * 2) = v;
    }
    __syncthreads();
    float acc[4][8];
    gemm_x2<192, 64>(sA, sWp, acc);
    const int rowg = tid & 31, colg = tid >> 5;
#pragma unroll
    for (int i = 0; i < 4; ++i) {
        int g = rowbase + rowg + 32 * i;
        if (g < nrows) {
            float o[8];
#pragma unroll
            for (int j = 0; j < 8; ++j) o[j] = acc[i][j] + sB[colg * 8 + j];
            float* dst = outp + (size_t)g * 64 + colg * 8;
            *(float4*)dst = make_float4(o[0], o[1], o[2], o[3]);
            *(float4*)(dst + 4) = make_float4(o[4], o[5], o[6], o[7]);
        }
    }
}

// BN1 stats only (no z1 store)
__global__ void __launch_bounds__(256) z1stats_kernel(const int* __restrict__ lu,
                                                      const int* __restrict__ lm) {
    __shared__ float sS[64], sQ[64];
    int tid = threadIdx.x;
    if (tid < 64) { sS[tid] = 0.f; sQ[tid] = 0.f; }
    __syncthreads();
    int lane = tid & 31;
    int gw = (blockIdx.x * 256 + tid) >> 5;
    int nw = gridDim.x * 8;
    float s0 = 0.f, s1 = 0.f, q0 = 0.f, q1 = 0.f;
    for (int r = gw; r < cEL; r += nw) {
        int u = __ldg(lu + r), m = __ldg(lm + r);
        float2 a = *(const float2*)(g_hu + (size_t)u * 64 + lane * 2);
        float2 b = *(const float2*)(g_hm + (size_t)m * 64 + lane * 2);
        float ox = a.x + b.x, oy = a.y + b.y;
        s0 += ox; s1 += oy; q0 += ox * ox; q1 += oy * oy;
    }
    atomicAdd(&sS[lane * 2], s0); atomicAdd(&sS[lane * 2 + 1], s1);
    atomicAdd(&sQ[lane * 2], q0); atomicAdd(&sQ[lane * 2 + 1], q1);
    __syncthreads();
    if (tid < 64) {
        atomicAdd(&g_stats[tid], (double)sS[tid]);
        atomicAdd(&g_stats[64 + tid], (double)sQ[tid]);
    }
}

__global__ void bn_finalize_kernel(int soff, int boff, int n,
                                   const float* __restrict__ gamma,
                                   const float* __restrict__ beta, float invc) {
    int t = threadIdx.x;
    if (t < n) {
        double m = g_stats[soff + t] * invc;
        double v = g_stats[soff + n + t] * invc - m * m;
        float sc = gamma[t] * rsqrtf((float)v + 1e-5f);
        g_bnp[boff + t] = sc;
        g_bnp[boff + n + t] = beta[t] - (float)m * sc;
    }
}

// z2 = bn1relu(P_u[lu]+P_m[lm]) @ W2 + b2; BN2 stats
__global__ void __launch_bounds__(256) z2_kernel(const int* __restrict__ lu,
                                                 const int* __restrict__ lm,
                                                 const float* __restrict__ W2,
                                                 const float* __restrict__ bias) {
    constexpr int LDA = 66;
    extern __shared__ float sm[];
    float* sA = sm;
    float2* sWp = (float2*)(sm + 128 * LDA);
    __shared__ float sB[32], sSc[64], sSh[64];
    __shared__ int sIU[128], sIM[128];
    const int tid = threadIdx.x, rowbase = blockIdx.x * 128;
    if (tid < 32) sB[tid] = bias[tid];
    if (tid < 64) { sSc[tid] = g_bnp[tid]; sSh[tid] = g_bnp[64 + tid]; }
    if (tid < 128) {
        int g = rowbase + tid;
        sIU[tid] = (g < cEL) ? __ldg(lu + g) : 0;
        sIM[tid] = (g < cEL) ? __ldg(lm + g) : 0;
    }
    stageWpair<64, 32>(sWp, W2, tid);
    __syncthreads();
    for (int idx = tid; idx < 128 * 32; idx += 256) {
        int r = idx >> 5, c2 = idx & 31, g = rowbase + r, c = c2 * 2;
        float2 v = make_float2(0.f, 0.f);
        if (g < cEL) {
            float2 a = *(const float2*)(g_hu + (size_t)sIU[r] * 64 + c);
            float2 b = *(const float2*)(g_hm + (size_t)sIM[r] * 64 + c);
            float zx = a.x + b.x, zy = a.y + b.y;
            v.x = fmaxf(zx * sSc[c] + sSh[c], 0.f);
            v.y = fmaxf(zy * sSc[c + 1] + sSh[c + 1], 0.f);
        }
        *(float2*)(sA + r * LDA + c) = v;
    }
    __syncthreads();
    float acc[4][4];
    gemm_x2<64, 32>(sA, sWp, acc);
    const int rowg = tid & 31, colg = tid >> 5;
    float ls[4] = {0}, lq[4] = {0};
#pragma unroll
    for (int i = 0; i < 4; ++i) {
        int g = rowbase + rowg + 32 * i;
        if (g < cEL) {
            float o[4];
#pragma unroll
            for (int j = 0; j < 4; ++j) {
                o[j] = acc[i][j] + sB[colg * 4 + j];
                ls[j] += o[j]; lq[j] += o[j] * o[j];
            }
            *(float4*)(g_z2 + (size_t)g * 32 + colg * 4) = make_float4(o[0], o[1], o[2], o[3]);
        }
    }
    __syncthreads();
#pragma unroll
    for (int j = 0; j < 4; ++j) {
        sA[rowg * 32 + colg * 4 + j] = ls[j];
        sA[1024 + rowg * 32 + colg * 4 + j] = lq[j];
    }
    __syncthreads();
    if (tid < 32) {
        float s = 0.f, q = 0.f;
        for (int g2 = 0; g2 < 32; ++g2) { s += sA[g2 * 32 + tid]; q += sA[1024 + g2 * 32 + tid]; }
        atomicAdd(&g_stats[128 + tid], (double)s);
        atomicAdd(&g_stats[160 + tid], (double)q);
    }
}

__global__ void __launch_bounds__(256) z3_kernel(const float* __restrict__ W3,
                                                 const float* __restrict__ b3,
                                                 float* __restrict__ out) {
    __shared__ float sW[32], sSc[32], sSh[32];
    int tid = threadIdx.x;
    if (tid < 32) { sW[tid] = W3[tid]; sSc[tid] = g_bnp[128 + tid]; sSh[tid] = g_bnp[160 + tid]; }
    __syncthreads();
    int g = blockIdx.x * 256 + tid;
    if (g < cEL) {
        const float* row = g_z2 + (size_t)g * 32;
        float acc = 0.f;
#pragma unroll
        for (int c = 0; c < 32; c += 4) {
            float4 v = *(const float4*)(row + c);
            acc += fmaxf(v.x * sSc[c] + sSh[c], 0.f) * sW[c];
            acc += fmaxf(v.y * sSc[c + 1] + sSh[c + 1], 0.f) * sW[c + 1];
            acc += fmaxf(v.z * sSc[c + 2] + sSh[c + 2], 0.f) * sW[c + 2];
            acc += fmaxf(v.w * sSc[c + 3] + sSh[c + 3], 0.f) * sW[c + 3];
        }
        out[g] = acc + b3[0];
    }
}

extern "C" void kernel_launch(void* const* d_in, const int* in_sizes, int n_in,
                              void* d_out, int out_size) {
    const int* n_id = (const int*)d_in[0];
    const float* movie_x = (const float*)d_in[1];
    const int* eu = (const int*)d_in[2];
    const int* em = (const int*)d_in[3];
    const int* lu = (const int*)d_in[4];
    const int* lm = (const int*)d_in[5];
    const float* user_emb = (const float*)d_in[6];
    const float* Wl_um = (const float*)d_in[7];
    const float* b_um = (const float*)d_in[8];
    const float* Wr_um = (const float*)d_in[9];
    const float* Wl_mu = (const float*)d_in[10];
    const float* b_mu = (const float*)d_in[11];
    const float* Wr_mu = (const float*)d_in[12];
    const float* proj_u_W = (const float*)d_in[13];
    const float* proj_u_b = (const float*)d_in[14];
    const float* proj_m_W = (const float*)d_in[15];
    const float* proj_m_b = (const float*)d_in[16];
    const float* W1 = (const float*)d_in[17];
    const float* b1 = (const float*)d_in[18];
    const float* g1 = (const float*)d_in[19];
    const float* be1 = (const float*)d_in[20];
    const float* W2 = (const float*)d_in[21];
    const float* b2 = (const float*)d_in[22];
    const float* g2 = (const float*)d_in[23];
    const float* be2 = (const float*)d_in[24];
    const float* W3 = (const float*)d_in[25];
    const float* b3 = (const float*)d_in[26];
    float* out = (float*)d_out;

    cudaFuncSetAttribute(sage_gemm_kernel, cudaFuncAttributeMaxDynamicSharedMemorySize, SAGE_SMEM);
    cudaFuncSetAttribute(user_sage_kernel, cudaFuncAttributeMaxDynamicSharedMemorySize, U64_SMEM);
    cudaFuncSetAttribute(linear64_kernel, cudaFuncAttributeMaxDynamicSharedMemorySize, U64_SMEM);
    cudaFuncSetAttribute(proj_gemm_kernel, cudaFuncAttributeMaxDynamicSharedMemorySize, PROJ_SMEM);
    cudaFuncSetAttribute(z2_kernel, cudaFuncAttributeMaxDynamicSharedMemorySize, Z2_SMEM);

    float* xu; cudaGetSymbolAddress((void**)&xu, g_xu0);
    float* cu; cudaGetSymbolAddress((void**)&cu, g_cat_u);
    float* cm; cudaGetSymbolAddress((void**)&cm, g_cat_m);
    float* am; cudaGetSymbolAddress((void**)&am, g_agg_m);
    float* ym; cudaGetSymbolAddress((void**)&ym, g_ym);

    zero_kernel<<<(cNU + 255) / 256, 256>>>();
    count_kernel<<<(cE + 255) / 256, 256>>>(eu, em);
    scan1_kernel<<<NBU + NBM, 1024>>>();
    scan2_kernel<<<2, 128>>>();
    scan3_kernel<<<(cNU + cNM + 255) / 256, 256>>>();
    fill_kernel<<<(cE + 255) / 256, 256>>>(eu, em);
    gather_u0_kernel<<<(cNU * 16 + 255) / 256, 256>>>(n_id, user_emb);
    wfuse_kernel<<<385, 64>>>(proj_u_W, proj_u_b, proj_m_W, proj_m_b, W1, b1);

    const int UB = (cNU + 127) / 128, MB = (cNM + 127) / 128;
    const int AGGB = ((cNU + cNM) * 32 + 255) / 256;
    for (int i = 0; i < 3; ++i) {
        const float* xup = i ? (cu + (i - 1) * 64) : xu;
        const float* xmp = i ? (cm + (i - 1) * 64) : movie_x;
        int ldu = i ? 192 : 64, ldm = i ? 192 : 64;
        linear64_kernel<<<MB, 256, U64_SMEM>>>(xmp, ldm, Wl_mu + i * 4096, ym, cNM);
        agg_both_kernel<<<AGGB, 256>>>(xup, ldu);
        sage_gemm_kernel<<<MB, 256, SAGE_SMEM>>>(am, xmp, ldm, Wl_um + i * 4096, Wr_um + i * 4096,
                                                 b_um + i * 64, cm + i * 64, cNM);
        user_sage_kernel<<<UB, 256, U64_SMEM>>>(xup, ldu, Wr_mu + i * 4096, b_mu + i * 64,
                                                cu + i * 64);
    }
    proj_gemm_kernel<<<UB + MB, 256, PROJ_SMEM>>>(UB);

    z1stats_kernel<<<1184, 256>>>(lu, lm);
    bn_finalize_kernel<<<1, 64>>>(0, 0, 64, g1, be1, 1.f / cEL);
    z2_kernel<<<(cEL + 127) / 128, 256, Z2_SMEM>>>(lu, lm, W2, b2);
    bn_finalize_kernel<<<1, 64>>>(128, 128, 32, g2, be2, 1.f / cEL);
    z3_kernel<<<(cEL + 255) / 256, 256>>>(W3, b3, out);
}